// round 3
// baseline (speedup 1.0000x reference)
#include <cuda_runtime.h>
#include <cuda_bf16.h>
#include <math.h>

// Problem constants
#define BB 32
#define TT 577
#define EE 1024
#define HH 16
#define DD 64
#define MM (BB * TT)   // 18464 rows

// Scratch (alloc-free rule: __device__ globals)
__device__ float g_q[(size_t)MM * EE];
__device__ float g_k[(size_t)MM * EE];
__device__ float g_v[(size_t)MM * EE];
__device__ float g_att[(size_t)MM * EE];

// ---------------------------------------------------------------------------
// SGEMM with bias: C[M,N] = A[M,K] @ B[K,N] + bias[N]
// BM=BN=128, BK=8, 256 threads, 8x8 register tile per thread.
// N and K assumed multiples of 128/8 (true here: 1024). M bounds-checked.
// ---------------------------------------------------------------------------
__global__ __launch_bounds__(256) void sgemm_bias_kernel(
    const float* __restrict__ A, const float* __restrict__ B,
    const float* __restrict__ bias, float* __restrict__ C,
    int M, int N, int K)
{
    constexpr int BM = 128, BN = 128, BK = 8, TM = 8, TN = 8;
    __shared__ float As[BK][BM];   // A tile stored transposed
    __shared__ float Bs[BK][BN];

    const int tid = threadIdx.x;
    const int tr = (tid >> 4) * TM;   // thread row offset in tile
    const int tc = (tid & 15) * TN;   // thread col offset in tile
    const int rowBase = blockIdx.y * BM;
    const int colBase = blockIdx.x * BN;

    // load mapping: A tile 128x8 -> 256 float4 (2 per row along K)
    const int aRow = tid >> 1;
    const int aCol = (tid & 1) * 4;
    // B tile 8x128 -> 256 float4
    const int bRow = tid >> 5;
    const int bCol = (tid & 31) * 4;

    float acc[TM][TN];
    #pragma unroll
    for (int i = 0; i < TM; i++)
        #pragma unroll
        for (int j = 0; j < TN; j++) acc[i][j] = 0.f;

    for (int k0 = 0; k0 < K; k0 += BK) {
        const int gRow = rowBase + aRow;
        float4 a4 = make_float4(0.f, 0.f, 0.f, 0.f);
        if (gRow < M)
            a4 = *(const float4*)(A + (size_t)gRow * K + k0 + aCol);
        As[aCol + 0][aRow] = a4.x;
        As[aCol + 1][aRow] = a4.y;
        As[aCol + 2][aRow] = a4.z;
        As[aCol + 3][aRow] = a4.w;

        float4 b4 = *(const float4*)(B + (size_t)(k0 + bRow) * N + colBase + bCol);
        *(float4*)&Bs[bRow][bCol] = b4;
        __syncthreads();

        #pragma unroll
        for (int kk = 0; kk < BK; kk++) {
            float ar[TM], br[TN];
            *(float4*)&ar[0] = *(const float4*)&As[kk][tr];
            *(float4*)&ar[4] = *(const float4*)&As[kk][tr + 4];
            *(float4*)&br[0] = *(const float4*)&Bs[kk][tc];
            *(float4*)&br[4] = *(const float4*)&Bs[kk][tc + 4];
            #pragma unroll
            for (int i = 0; i < TM; i++)
                #pragma unroll
                for (int j = 0; j < TN; j++)
                    acc[i][j] = fmaf(ar[i], br[j], acc[i][j]);
        }
        __syncthreads();
    }

    #pragma unroll
    for (int i = 0; i < TM; i++) {
        const int gRow = rowBase + tr + i;
        if (gRow < M) {
            #pragma unroll
            for (int j = 0; j < TN; j += 4) {
                const int gCol = colBase + tc + j;
                float4 o;
                o.x = acc[i][j + 0] + bias[gCol + 0];
                o.y = acc[i][j + 1] + bias[gCol + 1];
                o.z = acc[i][j + 2] + bias[gCol + 2];
                o.w = acc[i][j + 3] + bias[gCol + 3];
                *(float4*)(C + (size_t)gRow * N + gCol) = o;
            }
        }
    }
}

// ---------------------------------------------------------------------------
// Flash attention: per (b,h), per 64-query block. Key tiles of 32.
// q/k/v/o layouts: element (b,t,h,d) at ((b*T + t)*E + h*D + d), i.e. the
// natural [B,T,E] projection layout (no transpose materialization needed).
// ---------------------------------------------------------------------------
#define QB 64
#define KB 32

__global__ __launch_bounds__(256) void flash_attn_kernel(
    const float* __restrict__ q, const float* __restrict__ k,
    const float* __restrict__ v, float* __restrict__ o)
{
    const int bh = blockIdx.x;            // 0 .. B*H-1
    const int b = bh / HH;
    const int h = bh % HH;
    const int q0 = blockIdx.y * QB;

    const size_t base = (size_t)b * TT * EE + (size_t)h * DD;
    const float* Q = q + base;
    const float* K = k + base;
    const float* V = v + base;
    float* O = o + base;

    __shared__ float Qs[QB][DD + 4];   // stride 68
    __shared__ float Ks[KB][DD + 1];   // stride 65 (odd -> conflict-free row access)
    __shared__ float Vs[KB][DD + 4];   // stride 68
    __shared__ float Ps[QB][KB + 4];   // stride 36
    __shared__ float m_s[QB], l_s[QB], c_s[QB];

    const int tid = threadIdx.x;       // 256
    const int ty = tid >> 4;           // 0..15
    const int tx = tid & 15;           // 0..15

    // Load Q tile: 64 rows x 16 float4/row = 1024 float4, 4 per thread
    #pragma unroll
    for (int i = 0; i < 4; i++) {
        const int idx = tid + i * 256;
        const int r = idx >> 4;
        const int c4 = (idx & 15) << 2;
        const int gr = q0 + r;
        float4 val = make_float4(0.f, 0.f, 0.f, 0.f);
        if (gr < TT) val = *(const float4*)(Q + (size_t)gr * EE + c4);
        *(float4*)&Qs[r][c4] = val;
    }
    if (tid < QB) { m_s[tid] = -1e30f; l_s[tid] = 0.f; }

    float o_acc[4][4];
    #pragma unroll
    for (int a = 0; a < 4; a++)
        #pragma unroll
        for (int bb = 0; bb < 4; bb++) o_acc[a][bb] = 0.f;

    const int nkt = (TT + KB - 1) / KB;   // 19
    for (int kt = 0; kt < nkt; kt++) {
        __syncthreads();   // previous tile's Ps/Vs reads done; Qs visible (iter 0)

        // Load K,V tile: 32 rows x 16 float4 = 512 float4 each, 2 per thread
        #pragma unroll
        for (int i = 0; i < 2; i++) {
            const int idx = tid + i * 256;
            const int r = idx >> 4;
            const int c4 = (idx & 15) << 2;
            const int gr = kt * KB + r;
            float4 kv = make_float4(0.f, 0.f, 0.f, 0.f);
            float4 vv = make_float4(0.f, 0.f, 0.f, 0.f);
            if (gr < TT) {
                kv = *(const float4*)(K + (size_t)gr * EE + c4);
                vv = *(const float4*)(V + (size_t)gr * EE + c4);
            }
            Ks[r][c4 + 0] = kv.x; Ks[r][c4 + 1] = kv.y;
            Ks[r][c4 + 2] = kv.z; Ks[r][c4 + 3] = kv.w;
            *(float4*)&Vs[r][c4] = vv;
        }
        __syncthreads();

        // Scores: thread covers q rows ty*4+a (a<4), k cols tx*2+b (b<2)
        float s[4][2];
        #pragma unroll
        for (int a = 0; a < 4; a++) { s[a][0] = 0.f; s[a][1] = 0.f; }

        #pragma unroll 8
        for (int d = 0; d < DD; d++) {
            float kv0 = Ks[tx * 2 + 0][d];
            float kv1 = Ks[tx * 2 + 1][d];
            #pragma unroll
            for (int a = 0; a < 4; a++) {
                const float qv = Qs[ty * 4 + a][d];
                s[a][0] = fmaf(qv, kv0, s[a][0]);
                s[a][1] = fmaf(qv, kv1, s[a][1]);
            }
        }

        // Scale + mask + per-thread row max
        float tmax[4];
        #pragma unroll
        for (int a = 0; a < 4; a++) {
            tmax[a] = -1e30f;
            #pragma unroll
            for (int bb = 0; bb < 2; bb++) {
                const int kc = kt * KB + tx * 2 + bb;
                s[a][bb] = (kc < TT) ? s[a][bb] * 0.125f : -1e30f;
                tmax[a] = fmaxf(tmax[a], s[a][bb]);
            }
        }
        // Reduce max over the 16 tx lanes (lanes (ty&1)*16 + tx: xor 1,2,4,8
        // stays inside the 16-lane group)
        #pragma unroll
        for (int off = 8; off > 0; off >>= 1)
            #pragma unroll
            for (int a = 0; a < 4; a++)
                tmax[a] = fmaxf(tmax[a], __shfl_xor_sync(0xffffffffu, tmax[a], off));

        if (tx == 0) {
            #pragma unroll
            for (int a = 0; a < 4; a++) {
                const int r = ty * 4 + a;
                const float mo = m_s[r];
                const float mn = fmaxf(mo, tmax[a]);
                c_s[r] = __expf(mo - mn);
                m_s[r] = mn;
            }
        }
        __syncthreads();

        // P = exp(s - m), row sums, write P to smem
        float rs[4];
        #pragma unroll
        for (int a = 0; a < 4; a++) {
            const int r = ty * 4 + a;
            const float mrow = m_s[r];
            float p0 = __expf(s[a][0] - mrow);
            float p1 = __expf(s[a][1] - mrow);
            Ps[r][tx * 2 + 0] = p0;
            Ps[r][tx * 2 + 1] = p1;
            rs[a] = p0 + p1;
        }
        #pragma unroll
        for (int off = 8; off > 0; off >>= 1)
            #pragma unroll
            for (int a = 0; a < 4; a++)
                rs[a] += __shfl_xor_sync(0xffffffffu, rs[a], off);
        if (tx == 0) {
            #pragma unroll
            for (int a = 0; a < 4; a++) {
                const int r = ty * 4 + a;
                l_s[r] = l_s[r] * c_s[r] + rs[a];
            }
        }
        // Rescale O accumulator by correction factor
        #pragma unroll
        for (int a = 0; a < 4; a++) {
            const float c = c_s[ty * 4 + a];
            #pragma unroll
            for (int bb = 0; bb < 4; bb++) o_acc[a][bb] *= c;
        }
        __syncthreads();   // Ps complete

        // O += P @ V : thread covers q rows ty*4+a, d cols tx*4+b
        #pragma unroll 8
        for (int kk = 0; kk < KB; kk++) {
            float vv[4];
            #pragma unroll
            for (int bb = 0; bb < 4; bb++) vv[bb] = Vs[kk][tx * 4 + bb];
            #pragma unroll
            for (int a = 0; a < 4; a++) {
                const float pv = Ps[ty * 4 + a][kk];
                #pragma unroll
                for (int bb = 0; bb < 4; bb++)
                    o_acc[a][bb] = fmaf(pv, vv[bb], o_acc[a][bb]);
            }
        }
    }
    __syncthreads();

    // Epilogue: normalize and store
    #pragma unroll
    for (int a = 0; a < 4; a++) {
        const int r = ty * 4 + a;
        const int gr = q0 + r;
        if (gr < TT) {
            const float inv = 1.f / l_s[r];
            float4 ov;
            ov.x = o_acc[a][0] * inv;
            ov.y = o_acc[a][1] * inv;
            ov.z = o_acc[a][2] * inv;
            ov.w = o_acc[a][3] * inv;
            *(float4*)(O + (size_t)gr * EE + tx * 4) = ov;
        }
    }
}

// ---------------------------------------------------------------------------
// Launch
// ---------------------------------------------------------------------------
extern "C" void kernel_launch(void* const* d_in, const int* in_sizes, int n_in,
                              void* d_out, int out_size)
{
    const float* x  = (const float*)d_in[0];
    const float* Wq = (const float*)d_in[1];
    const float* bq = (const float*)d_in[2];
    const float* Wk = (const float*)d_in[3];
    const float* bk = (const float*)d_in[4];
    const float* Wv = (const float*)d_in[5];
    const float* bv = (const float*)d_in[6];
    const float* Wo = (const float*)d_in[7];
    const float* bo = (const float*)d_in[8];
    float* out = (float*)d_out;

    float *gq, *gk, *gv, *ga;
    cudaGetSymbolAddress((void**)&gq, g_q);
    cudaGetSymbolAddress((void**)&gk, g_k);
    cudaGetSymbolAddress((void**)&gv, g_v);
    cudaGetSymbolAddress((void**)&ga, g_att);

    dim3 gridG(EE / 128, (MM + 127) / 128);   // (8, 145)
    sgemm_bias_kernel<<<gridG, 256>>>(x, Wq, bq, gq, MM, EE, EE);
    sgemm_bias_kernel<<<gridG, 256>>>(x, Wk, bk, gk, MM, EE, EE);
    sgemm_bias_kernel<<<gridG, 256>>>(x, Wv, bv, gv, MM, EE, EE);

    dim3 gridA(BB * HH, (TT + QB - 1) / QB);  // (512, 10)
    flash_attn_kernel<<<gridA, 256>>>(gq, gk, gv, ga);

    sgemm_bias_kernel<<<gridG, 256>>>(ga, Wo, bo, out, MM, EE, EE);
}

// round 4
// speedup vs baseline: 2.1028x; 2.1028x over previous
#include <cuda_runtime.h>
#include <cuda_bf16.h>
#include <math.h>
#include <stdint.h>

// Problem constants
#define BB 32
#define TT 577
#define EE 1024
#define HH 16
#define DD 64
#define MM (BB * TT)   // 18464 rows

// Scratch (alloc-free rule: __device__ globals)
__device__ float g_q[(size_t)MM * EE];
__device__ float g_k[(size_t)MM * EE];
__device__ float g_v[(size_t)MM * EE];
__device__ float g_att[(size_t)MM * EE];

// ---------------------------------------------------------------------------
// 3xTF32 helpers
// ---------------------------------------------------------------------------
__device__ __forceinline__ void split_tf32(float x, float& hi, float& lo) {
    uint32_t uh;
    asm("cvt.rna.tf32.f32 %0, %1;" : "=r"(uh) : "f"(x));
    hi = __uint_as_float(uh);
    float r = x - hi;          // exact
    uint32_t ul;
    asm("cvt.rna.tf32.f32 %0, %1;" : "=r"(ul) : "f"(r));
    lo = __uint_as_float(ul);
}

__device__ __forceinline__ void mma_tf32(float* acc,
                                         uint32_t a0, uint32_t a1, uint32_t a2, uint32_t a3,
                                         uint32_t b0, uint32_t b1) {
    asm volatile(
        "mma.sync.aligned.m16n8k8.row.col.f32.tf32.tf32.f32 "
        "{%0,%1,%2,%3}, {%4,%5,%6,%7}, {%8,%9}, {%0,%1,%2,%3};\n"
        : "+f"(acc[0]), "+f"(acc[1]), "+f"(acc[2]), "+f"(acc[3])
        : "r"(a0), "r"(a1), "r"(a2), "r"(a3), "r"(b0), "r"(b1));
}

// ---------------------------------------------------------------------------
// GEMM (3xTF32): C[M,1024] = A[M,1024] @ B[1024,1024] + bias
// Block tile 128x128, BK=32, 8 warps (2x4), warp tile 64x32.
// Dynamic smem: AH/AL [2][128][36], BH/BL [2][32][136]  (143360 B)
// ---------------------------------------------------------------------------
#define GA_STRIDE 36
#define GB_STRIDE 136
#define GA_BUF (128 * GA_STRIDE)   // 4608 floats
#define GB_BUF (32 * GB_STRIDE)    // 4352 floats
#define GSMEM_FLOATS (2 * GA_BUF * 2 + 2 * GB_BUF * 2)   // 35840

__global__ __launch_bounds__(256) void gemm_tf32x3(
    const float* __restrict__ A, const float* __restrict__ B,
    const float* __restrict__ bias, float* __restrict__ C, int M)
{
    extern __shared__ float sm[];
    float* AH = sm;                   // [2][128][36]
    float* AL = AH + 2 * GA_BUF;
    float* BH = AL + 2 * GA_BUF;      // [2][32][136]
    float* BL = BH + 2 * GB_BUF;

    const int tid  = threadIdx.x;
    const int lane = tid & 31;
    const int wid  = tid >> 5;
    const int g    = lane >> 2;       // 0..7
    const int tg   = lane & 3;        // 0..3
    const int wm   = (wid >> 2) * 64; // warp row offset (0/64)
    const int wn   = (wid & 3) * 32;  // warp col offset (0/32/64/96)
    const int rowBase = blockIdx.y * 128;
    const int colBase = blockIdx.x * 128;

    float acc[4][4][4];
    #pragma unroll
    for (int mf = 0; mf < 4; mf++)
        #pragma unroll
        for (int nf = 0; nf < 4; nf++)
            #pragma unroll
            for (int c = 0; c < 4; c++) acc[mf][nf][c] = 0.f;

    // gmem->reg staging
    float4 aReg[4], bReg[4];

    auto loadA = [&](int k0) {
        #pragma unroll
        for (int i = 0; i < 4; i++) {
            const int idx = tid + i * 256;
            const int r = idx >> 3;
            const int c4 = (idx & 7) * 4;
            const int gr = rowBase + r;
            float4 v = make_float4(0.f, 0.f, 0.f, 0.f);
            if (gr < M) v = *(const float4*)(A + (size_t)gr * EE + k0 + c4);
            aReg[i] = v;
        }
    };
    auto loadB = [&](int k0) {
        #pragma unroll
        for (int i = 0; i < 4; i++) {
            const int idx = tid + i * 256;
            const int r = idx >> 5;
            const int c4 = (idx & 31) * 4;
            bReg[i] = *(const float4*)(B + (size_t)(k0 + r) * EE + colBase + c4);
        }
    };
    auto stage = [&](int buf) {
        float* ah = AH + buf * GA_BUF;
        float* al = AL + buf * GA_BUF;
        float* bh = BH + buf * GB_BUF;
        float* bl = BL + buf * GB_BUF;
        #pragma unroll
        for (int i = 0; i < 4; i++) {
            const int idx = tid + i * 256;
            const int r = idx >> 3;
            const int c4 = (idx & 7) * 4;
            float4 hv, lv;
            split_tf32(aReg[i].x, hv.x, lv.x);
            split_tf32(aReg[i].y, hv.y, lv.y);
            split_tf32(aReg[i].z, hv.z, lv.z);
            split_tf32(aReg[i].w, hv.w, lv.w);
            *(float4*)&ah[r * GA_STRIDE + c4] = hv;
            *(float4*)&al[r * GA_STRIDE + c4] = lv;
        }
        #pragma unroll
        for (int i = 0; i < 4; i++) {
            const int idx = tid + i * 256;
            const int r = idx >> 5;
            const int c4 = (idx & 31) * 4;
            float4 hv, lv;
            split_tf32(bReg[i].x, hv.x, lv.x);
            split_tf32(bReg[i].y, hv.y, lv.y);
            split_tf32(bReg[i].z, hv.z, lv.z);
            split_tf32(bReg[i].w, hv.w, lv.w);
            *(float4*)&bh[r * GB_STRIDE + c4] = hv;
            *(float4*)&bl[r * GB_STRIDE + c4] = lv;
        }
    };

    loadA(0); loadB(0);
    stage(0);
    __syncthreads();

    int buf = 0;
    for (int k0 = 0; k0 < EE; k0 += 32) {
        const bool more = (k0 + 32 < EE);
        if (more) { loadA(k0 + 32); loadB(k0 + 32); }

        const float* ah = AH + buf * GA_BUF;
        const float* al = AL + buf * GA_BUF;
        const float* bh = BH + buf * GB_BUF;
        const float* bl = BL + buf * GB_BUF;

        #pragma unroll
        for (int ks = 0; ks < 4; ks++) {
            uint32_t bHf[4][2], bLf[4][2];
            const int br0 = (ks * 8 + tg) * GB_STRIDE;
            const int br1 = (ks * 8 + tg + 4) * GB_STRIDE;
            #pragma unroll
            for (int nf = 0; nf < 4; nf++) {
                const int col = wn + nf * 8 + g;
                bHf[nf][0] = __float_as_uint(bh[br0 + col]);
                bHf[nf][1] = __float_as_uint(bh[br1 + col]);
                bLf[nf][0] = __float_as_uint(bl[br0 + col]);
                bLf[nf][1] = __float_as_uint(bl[br1 + col]);
            }
            #pragma unroll
            for (int mf = 0; mf < 4; mf++) {
                const int r0 = (wm + mf * 16 + g) * GA_STRIDE + ks * 8 + tg;
                const int r1 = r0 + 8 * GA_STRIDE;
                uint32_t aH0 = __float_as_uint(ah[r0]);
                uint32_t aH1 = __float_as_uint(ah[r1]);
                uint32_t aH2 = __float_as_uint(ah[r0 + 4]);
                uint32_t aH3 = __float_as_uint(ah[r1 + 4]);
                uint32_t aL0 = __float_as_uint(al[r0]);
                uint32_t aL1 = __float_as_uint(al[r1]);
                uint32_t aL2 = __float_as_uint(al[r0 + 4]);
                uint32_t aL3 = __float_as_uint(al[r1 + 4]);
                #pragma unroll
                for (int nf = 0; nf < 4; nf++) {
                    mma_tf32(acc[mf][nf], aH0, aH1, aH2, aH3, bHf[nf][0], bHf[nf][1]);
                    mma_tf32(acc[mf][nf], aL0, aL1, aL2, aL3, bHf[nf][0], bHf[nf][1]);
                    mma_tf32(acc[mf][nf], aH0, aH1, aH2, aH3, bLf[nf][0], bLf[nf][1]);
                }
            }
        }
        __syncthreads();
        if (more) {
            stage(buf ^ 1);
        }
        __syncthreads();
        buf ^= 1;
    }

    // Epilogue: C = acc + bias
    #pragma unroll
    for (int mf = 0; mf < 4; mf++) {
        const int row = rowBase + wm + mf * 16 + g;
        #pragma unroll
        for (int nf = 0; nf < 4; nf++) {
            const int col = colBase + wn + nf * 8 + 2 * tg;
            const float b0 = bias[col];
            const float b1 = bias[col + 1];
            if (row < M) {
                float2 o0 = make_float2(acc[mf][nf][0] + b0, acc[mf][nf][1] + b1);
                *(float2*)(C + (size_t)row * EE + col) = o0;
            }
            if (row + 8 < M) {
                float2 o1 = make_float2(acc[mf][nf][2] + b0, acc[mf][nf][3] + b1);
                *(float2*)(C + (size_t)(row + 8) * EE + col) = o1;
            }
        }
    }
}

// ---------------------------------------------------------------------------
// Flash attention, 128q x 128k tiles, 8x8 score tiles per thread,
// interleaved row ownership (ty+16a / tx+16b) for conflict-free smem.
// Softmax state (m,l) in registers, replicated per half-warp (16 tx lanes).
// Dynamic smem: Qs/Ks/Vs [128][68], Ps [128][132]  (172032 B)
// ---------------------------------------------------------------------------
#define FQB 128
#define FKB 128
#define FS_QKV 68
#define FS_P 132
#define FSMEM_FLOATS (3 * 128 * FS_QKV + 128 * FS_P)   // 43008

__global__ __launch_bounds__(256) void flash_attn_kernel(
    const float* __restrict__ q, const float* __restrict__ k,
    const float* __restrict__ v, float* __restrict__ o)
{
    extern __shared__ float sm[];
    float* Qs = sm;                      // [128][68]
    float* Ks = Qs + 128 * FS_QKV;
    float* Vs = Ks + 128 * FS_QKV;
    float* Ps = Vs + 128 * FS_QKV;       // [128][132]

    const int tid = threadIdx.x;
    const int ty = tid >> 4;             // 0..15
    const int tx = tid & 15;             // 0..15
    const int bh = blockIdx.x;
    const int b = bh >> 4;
    const int h = bh & 15;
    const int q0 = blockIdx.y * FQB;

    const size_t base = (size_t)b * TT * EE + (size_t)h * DD;
    const float* Q = q + base;
    const float* K = k + base;
    const float* V = v + base;
    float* O = o + base;

    // Load Q tile: 128 rows x 16 float4 = 2048 f4, 8 per thread
    #pragma unroll
    for (int i = 0; i < 8; i++) {
        const int idx = tid + i * 256;
        const int r = idx >> 4;
        const int c4 = (idx & 15) << 2;
        const int gr = q0 + r;
        float4 val = make_float4(0.f, 0.f, 0.f, 0.f);
        if (gr < TT) val = *(const float4*)(Q + (size_t)gr * EE + c4);
        *(float4*)&Qs[r * FS_QKV + c4] = val;
    }

    float m[8], l[8], oa[8][4];
    #pragma unroll
    for (int a = 0; a < 8; a++) {
        m[a] = -1e30f; l[a] = 0.f;
        #pragma unroll
        for (int j = 0; j < 4; j++) oa[a][j] = 0.f;
    }

    const int nkt = (TT + FKB - 1) / FKB;   // 5
    for (int kt = 0; kt < nkt; kt++) {
        const int kbase = kt * FKB;
        __syncthreads();   // protect Ks/Vs (prev iter readers done); Qs (iter 0)

        #pragma unroll
        for (int i = 0; i < 8; i++) {
            const int idx = tid + i * 256;
            const int r = idx >> 4;
            const int c4 = (idx & 15) << 2;
            const int gr = kbase + r;
            float4 kv = make_float4(0.f, 0.f, 0.f, 0.f);
            float4 vv = make_float4(0.f, 0.f, 0.f, 0.f);
            if (gr < TT) {
                kv = *(const float4*)(K + (size_t)gr * EE + c4);
                vv = *(const float4*)(V + (size_t)gr * EE + c4);
            }
            *(float4*)&Ks[r * FS_QKV + c4] = kv;
            *(float4*)&Vs[r * FS_QKV + c4] = vv;
        }
        __syncthreads();

        // ---- scores: s[a][b] = Q[ty+16a] . K[tx+16b] ----
        float s[8][8];
        #pragma unroll
        for (int a = 0; a < 8; a++)
            #pragma unroll
            for (int bb = 0; bb < 8; bb++) s[a][bb] = 0.f;

        #pragma unroll 2
        for (int d4 = 0; d4 < 16; d4++) {
            float4 kv[8];
            #pragma unroll
            for (int bb = 0; bb < 8; bb++)
                kv[bb] = *(const float4*)&Ks[(tx + 16 * bb) * FS_QKV + d4 * 4];
            #pragma unroll
            for (int a = 0; a < 8; a++) {
                const float4 qv = *(const float4*)&Qs[(ty + 16 * a) * FS_QKV + d4 * 4];
                #pragma unroll
                for (int bb = 0; bb < 8; bb++) {
                    s[a][bb] = fmaf(qv.x, kv[bb].x, s[a][bb]);
                    s[a][bb] = fmaf(qv.y, kv[bb].y, s[a][bb]);
                    s[a][bb] = fmaf(qv.z, kv[bb].z, s[a][bb]);
                    s[a][bb] = fmaf(qv.w, kv[bb].w, s[a][bb]);
                }
            }
        }

        // ---- scale, mask, row max (16 tx lanes = one half-warp per row) ----
        float mx[8];
        #pragma unroll
        for (int a = 0; a < 8; a++) {
            mx[a] = -1e30f;
            #pragma unroll
            for (int bb = 0; bb < 8; bb++) {
                const int kc = kbase + tx + 16 * bb;
                s[a][bb] = (kc < TT) ? s[a][bb] * 0.125f : -1e30f;
                mx[a] = fmaxf(mx[a], s[a][bb]);
            }
        }
        #pragma unroll
        for (int off = 8; off > 0; off >>= 1)
            #pragma unroll
            for (int a = 0; a < 8; a++)
                mx[a] = fmaxf(mx[a], __shfl_xor_sync(0xffffffffu, mx[a], off));

        // ---- softmax update (register state, identical across half-warp) ----
        float cc[8], rs[8];
        #pragma unroll
        for (int a = 0; a < 8; a++) {
            const float mn = fmaxf(m[a], mx[a]);
            cc[a] = __expf(m[a] - mn);
            m[a] = mn;
            float r = 0.f;
            const int prow = (ty + 16 * a) * FS_P + tx;
            #pragma unroll
            for (int bb = 0; bb < 8; bb++) {
                const float p = __expf(s[a][bb] - mn);
                Ps[prow + 16 * bb] = p;
                r += p;
            }
            rs[a] = r;
        }
        #pragma unroll
        for (int off = 8; off > 0; off >>= 1)
            #pragma unroll
            for (int a = 0; a < 8; a++)
                rs[a] += __shfl_xor_sync(0xffffffffu, rs[a], off);
        #pragma unroll
        for (int a = 0; a < 8; a++) {
            l[a] = l[a] * cc[a] + rs[a];
            #pragma unroll
            for (int j = 0; j < 4; j++) oa[a][j] *= cc[a];
        }
        __syncwarp();   // P rows are half-warp private; warp sync suffices

        // ---- O += P @ V : rows ty+16a, d cols tx*4..+3 ----
        #pragma unroll 2
        for (int kk = 0; kk < FKB; kk++) {
            const float4 vv = *(const float4*)&Vs[kk * FS_QKV + tx * 4];
            #pragma unroll
            for (int a = 0; a < 8; a++) {
                const float p = Ps[(ty + 16 * a) * FS_P + kk];
                oa[a][0] = fmaf(p, vv.x, oa[a][0]);
                oa[a][1] = fmaf(p, vv.y, oa[a][1]);
                oa[a][2] = fmaf(p, vv.z, oa[a][2]);
                oa[a][3] = fmaf(p, vv.w, oa[a][3]);
            }
        }
    }

    // ---- epilogue ----
    #pragma unroll
    for (int a = 0; a < 8; a++) {
        const int gr = q0 + ty + 16 * a;
        if (gr < TT) {
            const float inv = 1.f / l[a];
            float4 ov;
            ov.x = oa[a][0] * inv;
            ov.y = oa[a][1] * inv;
            ov.z = oa[a][2] * inv;
            ov.w = oa[a][3] * inv;
            *(float4*)(O + (size_t)gr * EE + tx * 4) = ov;
        }
    }
}

// ---------------------------------------------------------------------------
// Launch
// ---------------------------------------------------------------------------
extern "C" void kernel_launch(void* const* d_in, const int* in_sizes, int n_in,
                              void* d_out, int out_size)
{
    const float* x  = (const float*)d_in[0];
    const float* Wq = (const float*)d_in[1];
    const float* bq = (const float*)d_in[2];
    const float* Wk = (const float*)d_in[3];
    const float* bk = (const float*)d_in[4];
    const float* Wv = (const float*)d_in[5];
    const float* bv = (const float*)d_in[6];
    const float* Wo = (const float*)d_in[7];
    const float* bo = (const float*)d_in[8];
    float* out = (float*)d_out;

    float *gq, *gk, *gv, *ga;
    cudaGetSymbolAddress((void**)&gq, g_q);
    cudaGetSymbolAddress((void**)&gk, g_k);
    cudaGetSymbolAddress((void**)&gv, g_v);
    cudaGetSymbolAddress((void**)&ga, g_att);

    const int smemG = GSMEM_FLOATS * 4;   // 143360
    const int smemF = FSMEM_FLOATS * 4;   // 172032
    cudaFuncSetAttribute(gemm_tf32x3, cudaFuncAttributeMaxDynamicSharedMemorySize, smemG);
    cudaFuncSetAttribute(flash_attn_kernel, cudaFuncAttributeMaxDynamicSharedMemorySize, smemF);

    dim3 gridG(EE / 128, (MM + 127) / 128);   // (8, 145)
    gemm_tf32x3<<<gridG, 256, smemG>>>(x, Wq, bq, gq, MM);
    gemm_tf32x3<<<gridG, 256, smemG>>>(x, Wk, bk, gk, MM);
    gemm_tf32x3<<<gridG, 256, smemG>>>(x, Wv, bv, gv, MM);

    dim3 gridA(BB * HH, (TT + FQB - 1) / FQB);  // (512, 5)
    flash_attn_kernel<<<gridA, 256, smemF>>>(gq, gk, gv, ga);

    gemm_tf32x3<<<gridG, 256, smemG>>>(ga, Wo, bo, out, MM);
}

// round 5
// speedup vs baseline: 2.2497x; 1.0699x over previous
#include <cuda_runtime.h>
#include <cuda_bf16.h>
#include <math.h>
#include <stdint.h>

// Problem constants
#define BB 32
#define TT 577
#define EE 1024
#define HH 16
#define DD 64
#define MM (BB * TT)   // 18464 rows

// Scratch (alloc-free rule: __device__ globals)
__device__ float g_q[(size_t)MM * EE];
__device__ float g_k[(size_t)MM * EE];
__device__ float g_v[(size_t)MM * EE];
__device__ float g_att[(size_t)MM * EE];

// ---------------------------------------------------------------------------
// 3xTF32 helpers
// ---------------------------------------------------------------------------
__device__ __forceinline__ void split_tf32(float x, float& hi, float& lo) {
    uint32_t uh;
    asm("cvt.rna.tf32.f32 %0, %1;" : "=r"(uh) : "f"(x));
    hi = __uint_as_float(uh);
    float r = x - hi;          // exact
    uint32_t ul;
    asm("cvt.rna.tf32.f32 %0, %1;" : "=r"(ul) : "f"(r));
    lo = __uint_as_float(ul);
}

__device__ __forceinline__ void mma_tf32(float* acc,
                                         uint32_t a0, uint32_t a1, uint32_t a2, uint32_t a3,
                                         uint32_t b0, uint32_t b1) {
    asm volatile(
        "mma.sync.aligned.m16n8k8.row.col.f32.tf32.tf32.f32 "
        "{%0,%1,%2,%3}, {%4,%5,%6,%7}, {%8,%9}, {%0,%1,%2,%3};\n"
        : "+f"(acc[0]), "+f"(acc[1]), "+f"(acc[2]), "+f"(acc[3])
        : "r"(a0), "r"(a1), "r"(a2), "r"(a3), "r"(b0), "r"(b1));
}

// ---------------------------------------------------------------------------
// GEMM (3xTF32): C[M,1024] = A[M,1024] @ B[1024,1024] + bias
// Block tile 128x128, BK=32, 8 warps (2x4), warp tile 64x32.
// ---------------------------------------------------------------------------
#define GA_STRIDE 36
#define GB_STRIDE 136
#define GA_BUF (128 * GA_STRIDE)   // 4608 floats
#define GB_BUF (32 * GB_STRIDE)    // 4352 floats
#define GSMEM_FLOATS (2 * GA_BUF * 2 + 2 * GB_BUF * 2)   // 35840

__global__ __launch_bounds__(256) void gemm_tf32x3(
    const float* __restrict__ A, const float* __restrict__ B,
    const float* __restrict__ bias, float* __restrict__ C, int M)
{
    extern __shared__ float sm[];
    float* AH = sm;                   // [2][128][36]
    float* AL = AH + 2 * GA_BUF;
    float* BH = AL + 2 * GA_BUF;      // [2][32][136]
    float* BL = BH + 2 * GB_BUF;

    const int tid  = threadIdx.x;
    const int lane = tid & 31;
    const int wid  = tid >> 5;
    const int g    = lane >> 2;       // 0..7
    const int tg   = lane & 3;        // 0..3
    const int wm   = (wid >> 2) * 64; // warp row offset (0/64)
    const int wn   = (wid & 3) * 32;  // warp col offset (0/32/64/96)
    const int rowBase = blockIdx.y * 128;
    const int colBase = blockIdx.x * 128;

    float acc[4][4][4];
    #pragma unroll
    for (int mf = 0; mf < 4; mf++)
        #pragma unroll
        for (int nf = 0; nf < 4; nf++)
            #pragma unroll
            for (int c = 0; c < 4; c++) acc[mf][nf][c] = 0.f;

    float4 aReg[4], bReg[4];

    auto loadA = [&](int k0) {
        #pragma unroll
        for (int i = 0; i < 4; i++) {
            const int idx = tid + i * 256;
            const int r = idx >> 3;
            const int c4 = (idx & 7) * 4;
            const int gr = rowBase + r;
            float4 v = make_float4(0.f, 0.f, 0.f, 0.f);
            if (gr < M) v = *(const float4*)(A + (size_t)gr * EE + k0 + c4);
            aReg[i] = v;
        }
    };
    auto loadB = [&](int k0) {
        #pragma unroll
        for (int i = 0; i < 4; i++) {
            const int idx = tid + i * 256;
            const int r = idx >> 5;
            const int c4 = (idx & 31) * 4;
            bReg[i] = *(const float4*)(B + (size_t)(k0 + r) * EE + colBase + c4);
        }
    };
    auto stage = [&](int buf) {
        float* ah = AH + buf * GA_BUF;
        float* al = AL + buf * GA_BUF;
        float* bh = BH + buf * GB_BUF;
        float* bl = BL + buf * GB_BUF;
        #pragma unroll
        for (int i = 0; i < 4; i++) {
            const int idx = tid + i * 256;
            const int r = idx >> 3;
            const int c4 = (idx & 7) * 4;
            float4 hv, lv;
            split_tf32(aReg[i].x, hv.x, lv.x);
            split_tf32(aReg[i].y, hv.y, lv.y);
            split_tf32(aReg[i].z, hv.z, lv.z);
            split_tf32(aReg[i].w, hv.w, lv.w);
            *(float4*)&ah[r * GA_STRIDE + c4] = hv;
            *(float4*)&al[r * GA_STRIDE + c4] = lv;
        }
        #pragma unroll
        for (int i = 0; i < 4; i++) {
            const int idx = tid + i * 256;
            const int r = idx >> 5;
            const int c4 = (idx & 31) * 4;
            float4 hv, lv;
            split_tf32(bReg[i].x, hv.x, lv.x);
            split_tf32(bReg[i].y, hv.y, lv.y);
            split_tf32(bReg[i].z, hv.z, lv.z);
            split_tf32(bReg[i].w, hv.w, lv.w);
            *(float4*)&bh[r * GB_STRIDE + c4] = hv;
            *(float4*)&bl[r * GB_STRIDE + c4] = lv;
        }
    };

    loadA(0); loadB(0);
    stage(0);
    __syncthreads();

    int buf = 0;
    for (int k0 = 0; k0 < EE; k0 += 32) {
        const bool more = (k0 + 32 < EE);
        if (more) { loadA(k0 + 32); loadB(k0 + 32); }

        const float* ah = AH + buf * GA_BUF;
        const float* al = AL + buf * GA_BUF;
        const float* bh = BH + buf * GB_BUF;
        const float* bl = BL + buf * GB_BUF;

        #pragma unroll
        for (int ks = 0; ks < 4; ks++) {
            uint32_t bHf[4][2], bLf[4][2];
            const int br0 = (ks * 8 + tg) * GB_STRIDE;
            const int br1 = (ks * 8 + tg + 4) * GB_STRIDE;
            #pragma unroll
            for (int nf = 0; nf < 4; nf++) {
                const int col = wn + nf * 8 + g;
                bHf[nf][0] = __float_as_uint(bh[br0 + col]);
                bHf[nf][1] = __float_as_uint(bh[br1 + col]);
                bLf[nf][0] = __float_as_uint(bl[br0 + col]);
                bLf[nf][1] = __float_as_uint(bl[br1 + col]);
            }
            #pragma unroll
            for (int mf = 0; mf < 4; mf++) {
                const int r0 = (wm + mf * 16 + g) * GA_STRIDE + ks * 8 + tg;
                const int r1 = r0 + 8 * GA_STRIDE;
                uint32_t aH0 = __float_as_uint(ah[r0]);
                uint32_t aH1 = __float_as_uint(ah[r1]);
                uint32_t aH2 = __float_as_uint(ah[r0 + 4]);
                uint32_t aH3 = __float_as_uint(ah[r1 + 4]);
                uint32_t aL0 = __float_as_uint(al[r0]);
                uint32_t aL1 = __float_as_uint(al[r1]);
                uint32_t aL2 = __float_as_uint(al[r0 + 4]);
                uint32_t aL3 = __float_as_uint(al[r1 + 4]);
                #pragma unroll
                for (int nf = 0; nf < 4; nf++) {
                    mma_tf32(acc[mf][nf], aH0, aH1, aH2, aH3, bHf[nf][0], bHf[nf][1]);
                    mma_tf32(acc[mf][nf], aL0, aL1, aL2, aL3, bHf[nf][0], bHf[nf][1]);
                    mma_tf32(acc[mf][nf], aH0, aH1, aH2, aH3, bLf[nf][0], bLf[nf][1]);
                }
            }
        }
        // stage(buf^1) writes the other buffer — safe to overlap with lagging
        // readers of buf; single barrier orders stage -> next-iter reads and
        // this iter's reads -> next overwrite of buf.
        if (more) {
            stage(buf ^ 1);
        }
        __syncthreads();
        buf ^= 1;
    }

    #pragma unroll
    for (int mf = 0; mf < 4; mf++) {
        const int row = rowBase + wm + mf * 16 + g;
        #pragma unroll
        for (int nf = 0; nf < 4; nf++) {
            const int col = colBase + wn + nf * 8 + 2 * tg;
            const float b0 = bias[col];
            const float b1 = bias[col + 1];
            if (row < M) {
                float2 o0 = make_float2(acc[mf][nf][0] + b0, acc[mf][nf][1] + b1);
                *(float2*)(C + (size_t)row * EE + col) = o0;
            }
            if (row + 8 < M) {
                float2 o1 = make_float2(acc[mf][nf][2] + b0, acc[mf][nf][3] + b1);
                *(float2*)(C + (size_t)(row + 8) * EE + col) = o1;
            }
        }
    }
}

// ---------------------------------------------------------------------------
// Tensor-core flash attention (3xTF32 for S = QK^T and O += P V).
// Block: 128 q-rows; k-tiles of 64. 8 warps; warp w owns q rows [16w,16w+16).
// Softmax state in registers (2 rows/lane: g and g+8; reduce over 4 tg lanes).
// Strides: Q/K/P = 68 (banks 4g+tg distinct), V = 72 (banks 8tg+g distinct).
// Dynamic smem: Qh,Ql[128][68] Kh,Kl[64][68] Vh,Vl[64][72] Ph,Pl[128][68]
//             = 52736 floats = 210944 B
// ---------------------------------------------------------------------------
#define FQB 128
#define FKB 64
#define QS 68
#define KS 68
#define VS 72
#define PS 68
#define FSMEM_FLOATS (2*128*QS + 2*64*KS + 2*64*VS + 2*128*PS)   // 52736

__global__ __launch_bounds__(256) void flash_attn_tc(
    const float* __restrict__ q, const float* __restrict__ k,
    const float* __restrict__ v, float* __restrict__ o)
{
    extern __shared__ float sm[];
    float* Qh = sm;
    float* Ql = Qh + 128 * QS;
    float* Kh = Ql + 128 * QS;
    float* Kl = Kh + 64 * KS;
    float* Vh = Kl + 64 * KS;
    float* Vl = Vh + 64 * VS;
    float* Ph = Vl + 64 * VS;
    float* Pl = Ph + 128 * PS;

    const int tid  = threadIdx.x;
    const int lane = tid & 31;
    const int wid  = tid >> 5;       // 0..7
    const int g    = lane >> 2;      // 0..7
    const int tg   = lane & 3;       // 0..3

    const int bh = blockIdx.x;
    const int b = bh >> 4;
    const int h = bh & 15;
    const int q0 = blockIdx.y * FQB;

    const size_t base = (size_t)b * TT * EE + (size_t)h * DD;
    const float* Q = q + base;
    const float* K = k + base;
    const float* V = v + base;
    float* O = o + base;

    // ---- load + split Q tile: 128 x 64 = 2048 float4, 8 per thread ----
    #pragma unroll
    for (int i = 0; i < 8; i++) {
        const int idx = tid + i * 256;
        const int r = idx >> 4;
        const int c4 = (idx & 15) << 2;
        const int gr = q0 + r;
        float4 val = make_float4(0.f, 0.f, 0.f, 0.f);
        if (gr < TT) val = *(const float4*)(Q + (size_t)gr * EE + c4);
        float4 hv, lv;
        split_tf32(val.x, hv.x, lv.x);
        split_tf32(val.y, hv.y, lv.y);
        split_tf32(val.z, hv.z, lv.z);
        split_tf32(val.w, hv.w, lv.w);
        *(float4*)&Qh[r * QS + c4] = hv;
        *(float4*)&Ql[r * QS + c4] = lv;
    }

    float m0 = -1e30f, m1 = -1e30f, l0 = 0.f, l1 = 0.f;
    float oacc[8][4];
    #pragma unroll
    for (int nf = 0; nf < 8; nf++)
        #pragma unroll
        for (int c = 0; c < 4; c++) oacc[nf][c] = 0.f;

    const int row0 = 16 * wid + g;   // local q rows owned by this lane
    const int row1 = row0 + 8;

    const int nkt = (TT + FKB - 1) / FKB;   // 10
    for (int kt = 0; kt < nkt; kt++) {
        const int kbase = kt * FKB;
        __syncthreads();   // prev iter K/V/P readers done (and Q staged, iter 0)

        // ---- load + split K,V tile: 64 x 64 = 1024 f4 each, 4 per thread ----
        #pragma unroll
        for (int i = 0; i < 4; i++) {
            const int idx = tid + i * 256;
            const int r = idx >> 4;
            const int c4 = (idx & 15) << 2;
            const int gr = kbase + r;
            float4 kv = make_float4(0.f, 0.f, 0.f, 0.f);
            float4 vv = make_float4(0.f, 0.f, 0.f, 0.f);
            if (gr < TT) {
                kv = *(const float4*)(K + (size_t)gr * EE + c4);
                vv = *(const float4*)(V + (size_t)gr * EE + c4);
            }
            float4 hv, lv;
            split_tf32(kv.x, hv.x, lv.x);
            split_tf32(kv.y, hv.y, lv.y);
            split_tf32(kv.z, hv.z, lv.z);
            split_tf32(kv.w, hv.w, lv.w);
            *(float4*)&Kh[r * KS + c4] = hv;
            *(float4*)&Kl[r * KS + c4] = lv;
            split_tf32(vv.x, hv.x, lv.x);
            split_tf32(vv.y, hv.y, lv.y);
            split_tf32(vv.z, hv.z, lv.z);
            split_tf32(vv.w, hv.w, lv.w);
            *(float4*)&Vh[r * VS + c4] = hv;
            *(float4*)&Vl[r * VS + c4] = lv;
        }
        __syncthreads();

        // ---- S = Q K^T (3xTF32), warp computes 16 rows x 64 keys ----
        float sacc[8][4];
        #pragma unroll
        for (int nf = 0; nf < 8; nf++)
            #pragma unroll
            for (int c = 0; c < 4; c++) sacc[nf][c] = 0.f;

        #pragma unroll
        for (int kd = 0; kd < 8; kd++) {
            const int ar0 = row0 * QS + kd * 8 + tg;
            const int ar1 = ar0 + 8 * QS;
            const uint32_t aH0 = __float_as_uint(Qh[ar0]);
            const uint32_t aH1 = __float_as_uint(Qh[ar1]);
            const uint32_t aH2 = __float_as_uint(Qh[ar0 + 4]);
            const uint32_t aH3 = __float_as_uint(Qh[ar1 + 4]);
            const uint32_t aL0 = __float_as_uint(Ql[ar0]);
            const uint32_t aL1 = __float_as_uint(Ql[ar1]);
            const uint32_t aL2 = __float_as_uint(Ql[ar0 + 4]);
            const uint32_t aL3 = __float_as_uint(Ql[ar1 + 4]);
            #pragma unroll
            for (int nf = 0; nf < 8; nf++) {
                const int br = (8 * nf + g) * KS + kd * 8 + tg;
                const uint32_t bH0 = __float_as_uint(Kh[br]);
                const uint32_t bH1 = __float_as_uint(Kh[br + 4]);
                const uint32_t bL0 = __float_as_uint(Kl[br]);
                const uint32_t bL1 = __float_as_uint(Kl[br + 4]);
                mma_tf32(sacc[nf], aH0, aH1, aH2, aH3, bH0, bH1);
                mma_tf32(sacc[nf], aL0, aL1, aL2, aL3, bH0, bH1);
                mma_tf32(sacc[nf], aH0, aH1, aH2, aH3, bL0, bL1);
            }
        }

        // ---- scale + mask + row max ----
        float mx0 = -1e30f, mx1 = -1e30f;
        #pragma unroll
        for (int nf = 0; nf < 8; nf++) {
            const int kc0 = kbase + 8 * nf + 2 * tg;
            const int kc1 = kc0 + 1;
            sacc[nf][0] = (kc0 < TT) ? sacc[nf][0] * 0.125f : -1e30f;
            sacc[nf][1] = (kc1 < TT) ? sacc[nf][1] * 0.125f : -1e30f;
            sacc[nf][2] = (kc0 < TT) ? sacc[nf][2] * 0.125f : -1e30f;
            sacc[nf][3] = (kc1 < TT) ? sacc[nf][3] * 0.125f : -1e30f;
            mx0 = fmaxf(mx0, fmaxf(sacc[nf][0], sacc[nf][1]));
            mx1 = fmaxf(mx1, fmaxf(sacc[nf][2], sacc[nf][3]));
        }
        mx0 = fmaxf(mx0, __shfl_xor_sync(0xffffffffu, mx0, 1));
        mx0 = fmaxf(mx0, __shfl_xor_sync(0xffffffffu, mx0, 2));
        mx1 = fmaxf(mx1, __shfl_xor_sync(0xffffffffu, mx1, 1));
        mx1 = fmaxf(mx1, __shfl_xor_sync(0xffffffffu, mx1, 2));

        const float mn0 = fmaxf(m0, mx0);
        const float mn1 = fmaxf(m1, mx1);
        const float cc0 = __expf(m0 - mn0);
        const float cc1 = __expf(m1 - mn1);
        m0 = mn0; m1 = mn1;

        // ---- P = exp(s - m): split + store to smem, accumulate row sums ----
        float rs0 = 0.f, rs1 = 0.f;
        #pragma unroll
        for (int nf = 0; nf < 8; nf++) {
            const float p0 = __expf(sacc[nf][0] - m0);
            const float p1 = __expf(sacc[nf][1] - m0);
            const float p2 = __expf(sacc[nf][2] - m1);
            const float p3 = __expf(sacc[nf][3] - m1);
            rs0 += p0 + p1;
            rs1 += p2 + p3;
            float h0, lo0, h1, lo1;
            const int col = 8 * nf + 2 * tg;
            split_tf32(p0, h0, lo0);
            split_tf32(p1, h1, lo1);
            *(float2*)&Ph[row0 * PS + col] = make_float2(h0, h1);
            *(float2*)&Pl[row0 * PS + col] = make_float2(lo0, lo1);
            split_tf32(p2, h0, lo0);
            split_tf32(p3, h1, lo1);
            *(float2*)&Ph[row1 * PS + col] = make_float2(h0, h1);
            *(float2*)&Pl[row1 * PS + col] = make_float2(lo0, lo1);
        }
        rs0 += __shfl_xor_sync(0xffffffffu, rs0, 1);
        rs0 += __shfl_xor_sync(0xffffffffu, rs0, 2);
        rs1 += __shfl_xor_sync(0xffffffffu, rs1, 1);
        rs1 += __shfl_xor_sync(0xffffffffu, rs1, 2);
        l0 = l0 * cc0 + rs0;
        l1 = l1 * cc1 + rs1;

        #pragma unroll
        for (int nf = 0; nf < 8; nf++) {
            oacc[nf][0] *= cc0;
            oacc[nf][1] *= cc0;
            oacc[nf][2] *= cc1;
            oacc[nf][3] *= cc1;
        }
        __syncwarp();   // P rows are warp-private: cross-lane visibility

        // ---- O += P V (3xTF32) ----
        #pragma unroll
        for (int kc = 0; kc < 8; kc++) {
            const int ar0 = row0 * PS + kc * 8 + tg;
            const int ar1 = ar0 + 8 * PS;
            const uint32_t aH0 = __float_as_uint(Ph[ar0]);
            const uint32_t aH1 = __float_as_uint(Ph[ar1]);
            const uint32_t aH2 = __float_as_uint(Ph[ar0 + 4]);
            const uint32_t aH3 = __float_as_uint(Ph[ar1 + 4]);
            const uint32_t aL0 = __float_as_uint(Pl[ar0]);
            const uint32_t aL1 = __float_as_uint(Pl[ar1]);
            const uint32_t aL2 = __float_as_uint(Pl[ar0 + 4]);
            const uint32_t aL3 = __float_as_uint(Pl[ar1 + 4]);
            #pragma unroll
            for (int nfd = 0; nfd < 8; nfd++) {
                const int br0 = (kc * 8 + tg) * VS + nfd * 8 + g;
                const int br1 = br0 + 4 * VS;
                const uint32_t bH0 = __float_as_uint(Vh[br0]);
                const uint32_t bH1 = __float_as_uint(Vh[br1]);
                const uint32_t bL0 = __float_as_uint(Vl[br0]);
                const uint32_t bL1 = __float_as_uint(Vl[br1]);
                mma_tf32(oacc[nfd], aH0, aH1, aH2, aH3, bH0, bH1);
                mma_tf32(oacc[nfd], aL0, aL1, aL2, aL3, bH0, bH1);
                mma_tf32(oacc[nfd], aH0, aH1, aH2, aH3, bL0, bL1);
            }
        }
    }

    // ---- epilogue: normalize + store ----
    const float inv0 = 1.f / l0;
    const float inv1 = 1.f / l1;
    const int gr0 = q0 + row0;
    const int gr1 = q0 + row1;
    #pragma unroll
    for (int nfd = 0; nfd < 8; nfd++) {
        const int col = nfd * 8 + 2 * tg;
        if (gr0 < TT)
            *(float2*)(O + (size_t)gr0 * EE + col) =
                make_float2(oacc[nfd][0] * inv0, oacc[nfd][1] * inv0);
        if (gr1 < TT)
            *(float2*)(O + (size_t)gr1 * EE + col) =
                make_float2(oacc[nfd][2] * inv1, oacc[nfd][3] * inv1);
    }
}

// ---------------------------------------------------------------------------
// Launch
// ---------------------------------------------------------------------------
extern "C" void kernel_launch(void* const* d_in, const int* in_sizes, int n_in,
                              void* d_out, int out_size)
{
    const float* x  = (const float*)d_in[0];
    const float* Wq = (const float*)d_in[1];
    const float* bq = (const float*)d_in[2];
    const float* Wk = (const float*)d_in[3];
    const float* bk = (const float*)d_in[4];
    const float* Wv = (const float*)d_in[5];
    const float* bv = (const float*)d_in[6];
    const float* Wo = (const float*)d_in[7];
    const float* bo = (const float*)d_in[8];
    float* out = (float*)d_out;

    float *gq, *gk, *gv, *ga;
    cudaGetSymbolAddress((void**)&gq, g_q);
    cudaGetSymbolAddress((void**)&gk, g_k);
    cudaGetSymbolAddress((void**)&gv, g_v);
    cudaGetSymbolAddress((void**)&ga, g_att);

    const int smemG = GSMEM_FLOATS * 4;   // 143360
    const int smemF = FSMEM_FLOATS * 4;   // 210944
    cudaFuncSetAttribute(gemm_tf32x3, cudaFuncAttributeMaxDynamicSharedMemorySize, smemG);
    cudaFuncSetAttribute(flash_attn_tc, cudaFuncAttributeMaxDynamicSharedMemorySize, smemF);

    dim3 gridG(EE / 128, (MM + 127) / 128);   // (8, 145)
    gemm_tf32x3<<<gridG, 256, smemG>>>(x, Wq, bq, gq, MM);
    gemm_tf32x3<<<gridG, 256, smemG>>>(x, Wk, bk, gk, MM);
    gemm_tf32x3<<<gridG, 256, smemG>>>(x, Wv, bv, gv, MM);

    dim3 gridA(BB * HH, (TT + FQB - 1) / FQB);  // (512, 5)
    flash_attn_tc<<<gridA, 256, smemF>>>(gq, gk, gv, ga);

    gemm_tf32x3<<<gridG, 256, smemG>>>(ga, Wo, bo, out, MM);
}

// round 7
// speedup vs baseline: 2.3920x; 1.0632x over previous
#include <cuda_runtime.h>
#include <cuda_bf16.h>
#include <math.h>
#include <stdint.h>

// Problem constants
#define BB 32
#define TT 577
#define EE 1024
#define HH 16
#define DD 64
#define MM (BB * TT)   // 18464 rows

// Scratch (alloc-free rule: __device__ globals)
__device__ float g_q[(size_t)MM * EE];
__device__ float g_k[(size_t)MM * EE];
__device__ float g_v[(size_t)MM * EE];
__device__ float g_att[(size_t)MM * EE];

// ---------------------------------------------------------------------------
// helpers
// ---------------------------------------------------------------------------
__device__ __forceinline__ void split_tf32(float x, float& hi, float& lo) {
    uint32_t uh;
    asm("cvt.rna.tf32.f32 %0, %1;" : "=r"(uh) : "f"(x));
    hi = __uint_as_float(uh);
    float r = x - hi;          // exact
    uint32_t ul;
    asm("cvt.rna.tf32.f32 %0, %1;" : "=r"(ul) : "f"(r));
    lo = __uint_as_float(ul);
}

__device__ __forceinline__ void split_u(float x, uint32_t& hi, uint32_t& lo) {
    float h, l;
    split_tf32(x, h, l);
    hi = __float_as_uint(h);
    lo = __float_as_uint(l);
}

__device__ __forceinline__ void mma_tf32(float* acc,
                                         uint32_t a0, uint32_t a1, uint32_t a2, uint32_t a3,
                                         uint32_t b0, uint32_t b1) {
    asm volatile(
        "mma.sync.aligned.m16n8k8.row.col.f32.tf32.tf32.f32 "
        "{%0,%1,%2,%3}, {%4,%5,%6,%7}, {%8,%9}, {%0,%1,%2,%3};\n"
        : "+f"(acc[0]), "+f"(acc[1]), "+f"(acc[2]), "+f"(acc[3])
        : "r"(a0), "r"(a1), "r"(a2), "r"(a3), "r"(b0), "r"(b1));
}

__device__ __forceinline__ uint32_t smem_u32(const void* p) {
    return (uint32_t)__cvta_generic_to_shared(p);
}

// cp.async 16B with zero-fill when pred is false (src not accessed)
__device__ __forceinline__ void cp16(uint32_t dst, const void* src, bool pred) {
    asm volatile("cp.async.cg.shared.global [%0], [%1], 16, %2;\n"
                 :: "r"(dst), "l"(src), "r"(pred ? 16 : 0));
}
#define CP_COMMIT() asm volatile("cp.async.commit_group;\n" ::: "memory")
#define CP_WAIT0()  asm volatile("cp.async.wait_group 0;\n" ::: "memory")

// ---------------------------------------------------------------------------
// GEMM (3xTF32): C[M,1024] = A[M,1024] @ B[1024,1024] + bias
// Block tile 128x128, BK=32, 8 warps (2x4), warp tile 64x32.
// fp32 in smem (single copy, cp.async staged); tf32 split at frag load.
// Dynamic smem: AS[2][128][36] + BS[2][32][136] = 71680 B -> 2 CTAs/SM.
// ---------------------------------------------------------------------------
#define GA_STRIDE 36
#define GB_STRIDE 136
#define GA_BUF (128 * GA_STRIDE)   // 4608 floats
#define GB_BUF (32 * GB_STRIDE)    // 4352 floats
#define GSMEM_FLOATS (2 * (GA_BUF + GB_BUF))   // 17920

__global__ __launch_bounds__(256, 2) void gemm_tf32x3(
    const float* __restrict__ A, const float* __restrict__ B,
    const float* __restrict__ bias, float* __restrict__ C, int M)
{
    extern __shared__ float sm[];
    float* AS = sm;                   // [2][128][36]
    float* BS = AS + 2 * GA_BUF;      // [2][32][136]
    const uint32_t sA = smem_u32(AS);
    const uint32_t sB = smem_u32(BS);

    const int tid  = threadIdx.x;
    const int lane = tid & 31;
    const int wid  = tid >> 5;
    const int g    = lane >> 2;       // 0..7
    const int tg   = lane & 3;        // 0..3
    const int wm   = (wid >> 2) * 64; // warp row offset (0/64)
    const int wn   = (wid & 3) * 32;  // warp col offset (0/32/64/96)
    const int rowBase = blockIdx.y * 128;
    const int colBase = blockIdx.x * 128;

    float acc[4][4][4];
    #pragma unroll
    for (int mf = 0; mf < 4; mf++)
        #pragma unroll
        for (int nf = 0; nf < 4; nf++)
            #pragma unroll
            for (int c = 0; c < 4; c++) acc[mf][nf][c] = 0.f;

    auto issue = [&](int buf, int k0) {
        #pragma unroll
        for (int i = 0; i < 4; i++) {
            const int idx = tid + i * 256;
            const int r = idx >> 3;
            const int c4 = (idx & 7) * 4;
            const int gr = rowBase + r;
            cp16(sA + (uint32_t)(buf * GA_BUF + r * GA_STRIDE + c4) * 4,
                 A + (size_t)gr * EE + k0 + c4, gr < M);
        }
        #pragma unroll
        for (int i = 0; i < 4; i++) {
            const int idx = tid + i * 256;
            const int r = idx >> 5;
            const int c4 = (idx & 31) * 4;
            cp16(sB + (uint32_t)(buf * GB_BUF + r * GB_STRIDE + c4) * 4,
                 B + (size_t)(k0 + r) * EE + colBase + c4, true);
        }
        CP_COMMIT();
    };

    issue(0, 0);
    CP_WAIT0();
    __syncthreads();

    int buf = 0;
    for (int k0 = 0; k0 < EE; k0 += 32) {
        const bool more = (k0 + 32 < EE);
        if (more) issue(buf ^ 1, k0 + 32);   // DMA overlaps compute below

        const float* as = AS + buf * GA_BUF;
        const float* bs = BS + buf * GB_BUF;

        #pragma unroll
        for (int ks = 0; ks < 4; ks++) {
            uint32_t bHf[4][2], bLf[4][2];
            const int br0 = (ks * 8 + tg) * GB_STRIDE;
            const int br1 = br0 + 4 * GB_STRIDE;
            #pragma unroll
            for (int nf = 0; nf < 4; nf++) {
                const int col = wn + nf * 8 + g;
                split_u(bs[br0 + col], bHf[nf][0], bLf[nf][0]);
                split_u(bs[br1 + col], bHf[nf][1], bLf[nf][1]);
            }
            #pragma unroll
            for (int mf = 0; mf < 4; mf++) {
                const int r0 = (wm + mf * 16 + g) * GA_STRIDE + ks * 8 + tg;
                const int r1 = r0 + 8 * GA_STRIDE;
                uint32_t aH0, aH1, aH2, aH3, aL0, aL1, aL2, aL3;
                split_u(as[r0],     aH0, aL0);
                split_u(as[r1],     aH1, aL1);
                split_u(as[r0 + 4], aH2, aL2);
                split_u(as[r1 + 4], aH3, aL3);
                #pragma unroll
                for (int nf = 0; nf < 4; nf++) {
                    mma_tf32(acc[mf][nf], aH0, aH1, aH2, aH3, bHf[nf][0], bHf[nf][1]);
                    mma_tf32(acc[mf][nf], aL0, aL1, aL2, aL3, bHf[nf][0], bHf[nf][1]);
                    mma_tf32(acc[mf][nf], aH0, aH1, aH2, aH3, bLf[nf][0], bLf[nf][1]);
                }
            }
        }
        if (more) CP_WAIT0();
        __syncthreads();
        buf ^= 1;
    }

    #pragma unroll
    for (int mf = 0; mf < 4; mf++) {
        const int row = rowBase + wm + mf * 16 + g;
        #pragma unroll
        for (int nf = 0; nf < 4; nf++) {
            const int col = colBase + wn + nf * 8 + 2 * tg;
            const float b0 = bias[col];
            const float b1 = bias[col + 1];
            if (row < M) {
                float2 o0 = make_float2(acc[mf][nf][0] + b0, acc[mf][nf][1] + b1);
                *(float2*)(C + (size_t)row * EE + col) = o0;
            }
            if (row + 8 < M) {
                float2 o1 = make_float2(acc[mf][nf][2] + b0, acc[mf][nf][3] + b1);
                *(float2*)(C + (size_t)(row + 8) * EE + col) = o1;
            }
        }
    }
}

// ---------------------------------------------------------------------------
// Tensor-core flash attention (3xTF32), fp32 smem, register split.
// Block: 128 q-rows; k-tiles of 64. 8 warps; warp w owns q rows [16w,16w+16).
// Dynamic smem: Qs[128][68] Ks[64][68] Vs[64][72] Ps[128][68]
//             = 26368 floats = 105472 B -> 2 CTAs/SM.
// ---------------------------------------------------------------------------
#define FQB 128
#define FKB 64
#define QS 68
#define KS 68
#define VS 72
#define PS 68
#define FSMEM_FLOATS (128*QS + 64*KS + 64*VS + 128*PS)   // 26368

__global__ __launch_bounds__(256, 2) void flash_attn_tc(
    const float* __restrict__ q, const float* __restrict__ k,
    const float* __restrict__ v, float* __restrict__ o)
{
    extern __shared__ float sm[];
    float* Qs = sm;
    float* Ks = Qs + 128 * QS;
    float* Vs = Ks + 64 * KS;
    float* Ps = Vs + 64 * VS;
    const uint32_t sQ = smem_u32(Qs);
    const uint32_t sK = smem_u32(Ks);
    const uint32_t sV = smem_u32(Vs);

    const int tid  = threadIdx.x;
    const int lane = tid & 31;
    const int wid  = tid >> 5;       // 0..7
    const int g    = lane >> 2;      // 0..7
    const int tg   = lane & 3;       // 0..3

    const int bh = blockIdx.x;
    const int b = bh >> 4;
    const int h = bh & 15;
    const int q0 = blockIdx.y * FQB;

    const size_t base = (size_t)b * TT * EE + (size_t)h * DD;
    const float* Q = q + base;
    const float* K = k + base;
    const float* V = v + base;
    float* O = o + base;

    // ---- stage Q tile via cp.async: 128 rows x 16 chunks = 2048 ----
    #pragma unroll
    for (int i = 0; i < 8; i++) {
        const int idx = tid + i * 256;
        const int r = idx >> 4;
        const int c4 = (idx & 15) << 2;
        const int gr = q0 + r;
        cp16(sQ + (uint32_t)(r * QS + c4) * 4, Q + (size_t)gr * EE + c4, gr < TT);
    }
    CP_COMMIT();

    float m0 = -1e30f, m1 = -1e30f, l0 = 0.f, l1 = 0.f;
    float oacc[8][4];
    #pragma unroll
    for (int nf = 0; nf < 8; nf++)
        #pragma unroll
        for (int c = 0; c < 4; c++) oacc[nf][c] = 0.f;

    const int row0 = 16 * wid + g;   // local q rows owned by this lane
    const int row1 = row0 + 8;

    const int nkt = (TT + FKB - 1) / FKB;   // 10
    for (int kt = 0; kt < nkt; kt++) {
        const int kbase = kt * FKB;
        __syncthreads();   // prev iter K/V readers done

        // ---- stage K,V tile: 64 rows x 16 chunks = 1024 each ----
        #pragma unroll
        for (int i = 0; i < 4; i++) {
            const int idx = tid + i * 256;
            const int r = idx >> 4;
            const int c4 = (idx & 15) << 2;
            const int gr = kbase + r;
            cp16(sK + (uint32_t)(r * KS + c4) * 4, K + (size_t)gr * EE + c4, gr < TT);
            cp16(sV + (uint32_t)(r * VS + c4) * 4, V + (size_t)gr * EE + c4, gr < TT);
        }
        CP_COMMIT();
        CP_WAIT0();          // also covers the Q group on iter 0
        __syncthreads();

        // ---- S = Q K^T (3xTF32), warp computes 16 rows x 64 keys ----
        float sacc[8][4];
        #pragma unroll
        for (int nf = 0; nf < 8; nf++)
            #pragma unroll
            for (int c = 0; c < 4; c++) sacc[nf][c] = 0.f;

        #pragma unroll
        for (int kd = 0; kd < 8; kd++) {
            const int ar0 = row0 * QS + kd * 8 + tg;
            const int ar1 = ar0 + 8 * QS;
            uint32_t aH0, aH1, aH2, aH3, aL0, aL1, aL2, aL3;
            split_u(Qs[ar0],     aH0, aL0);
            split_u(Qs[ar1],     aH1, aL1);
            split_u(Qs[ar0 + 4], aH2, aL2);
            split_u(Qs[ar1 + 4], aH3, aL3);
            #pragma unroll
            for (int nf = 0; nf < 8; nf++) {
                const int br = (8 * nf + g) * KS + kd * 8 + tg;
                uint32_t bH0, bH1, bL0, bL1;
                split_u(Ks[br],     bH0, bL0);
                split_u(Ks[br + 4], bH1, bL1);
                mma_tf32(sacc[nf], aH0, aH1, aH2, aH3, bH0, bH1);
                mma_tf32(sacc[nf], aL0, aL1, aL2, aL3, bH0, bH1);
                mma_tf32(sacc[nf], aH0, aH1, aH2, aH3, bL0, bL1);
            }
        }

        // ---- scale + mask + row max ----
        float mx0 = -1e30f, mx1 = -1e30f;
        #pragma unroll
        for (int nf = 0; nf < 8; nf++) {
            const int kc0 = kbase + 8 * nf + 2 * tg;
            const int kc1 = kc0 + 1;
            sacc[nf][0] = (kc0 < TT) ? sacc[nf][0] * 0.125f : -1e30f;
            sacc[nf][1] = (kc1 < TT) ? sacc[nf][1] * 0.125f : -1e30f;
            sacc[nf][2] = (kc0 < TT) ? sacc[nf][2] * 0.125f : -1e30f;
            sacc[nf][3] = (kc1 < TT) ? sacc[nf][3] * 0.125f : -1e30f;
            mx0 = fmaxf(mx0, fmaxf(sacc[nf][0], sacc[nf][1]));
            mx1 = fmaxf(mx1, fmaxf(sacc[nf][2], sacc[nf][3]));
        }
        mx0 = fmaxf(mx0, __shfl_xor_sync(0xffffffffu, mx0, 1));
        mx0 = fmaxf(mx0, __shfl_xor_sync(0xffffffffu, mx0, 2));
        mx1 = fmaxf(mx1, __shfl_xor_sync(0xffffffffu, mx1, 1));
        mx1 = fmaxf(mx1, __shfl_xor_sync(0xffffffffu, mx1, 2));

        const float mn0 = fmaxf(m0, mx0);
        const float mn1 = fmaxf(m1, mx1);
        const float cc0 = __expf(m0 - mn0);
        const float cc1 = __expf(m1 - mn1);
        m0 = mn0; m1 = mn1;

        // ---- P = exp(s - m): store fp32 to smem, accumulate row sums ----
        float rs0 = 0.f, rs1 = 0.f;
        #pragma unroll
        for (int nf = 0; nf < 8; nf++) {
            const float p0 = __expf(sacc[nf][0] - m0);
            const float p1 = __expf(sacc[nf][1] - m0);
            const float p2 = __expf(sacc[nf][2] - m1);
            const float p3 = __expf(sacc[nf][3] - m1);
            rs0 += p0 + p1;
            rs1 += p2 + p3;
            const int col = 8 * nf + 2 * tg;
            *(float2*)&Ps[row0 * PS + col] = make_float2(p0, p1);
            *(float2*)&Ps[row1 * PS + col] = make_float2(p2, p3);
        }
        rs0 += __shfl_xor_sync(0xffffffffu, rs0, 1);
        rs0 += __shfl_xor_sync(0xffffffffu, rs0, 2);
        rs1 += __shfl_xor_sync(0xffffffffu, rs1, 1);
        rs1 += __shfl_xor_sync(0xffffffffu, rs1, 2);
        l0 = l0 * cc0 + rs0;
        l1 = l1 * cc1 + rs1;

        #pragma unroll
        for (int nf = 0; nf < 8; nf++) {
            oacc[nf][0] *= cc0;
            oacc[nf][1] *= cc0;
            oacc[nf][2] *= cc1;
            oacc[nf][3] *= cc1;
        }
        __syncwarp();   // P rows are warp-private: cross-lane visibility

        // ---- O += P V (3xTF32) ----
        #pragma unroll
        for (int kc = 0; kc < 8; kc++) {
            const int ar0 = row0 * PS + kc * 8 + tg;
            const int ar1 = ar0 + 8 * PS;
            uint32_t aH0, aH1, aH2, aH3, aL0, aL1, aL2, aL3;
            split_u(Ps[ar0],     aH0, aL0);
            split_u(Ps[ar1],     aH1, aL1);
            split_u(Ps[ar0 + 4], aH2, aL2);
            split_u(Ps[ar1 + 4], aH3, aL3);
            #pragma unroll
            for (int nfd = 0; nfd < 8; nfd++) {
                const int br0 = (kc * 8 + tg) * VS + nfd * 8 + g;
                const int br1 = br0 + 4 * VS;
                uint32_t bH0, bH1, bL0, bL1;
                split_u(Vs[br0], bH0, bL0);
                split_u(Vs[br1], bH1, bL1);
                mma_tf32(oacc[nfd], aH0, aH1, aH2, aH3, bH0, bH1);
                mma_tf32(oacc[nfd], aL0, aL1, aL2, aL3, bH0, bH1);
                mma_tf32(oacc[nfd], aH0, aH1, aH2, aH3, bL0, bL1);
            }
        }
    }

    // ---- epilogue: normalize + store ----
    const float inv0 = 1.f / l0;
    const float inv1 = 1.f / l1;
    const int gr0 = q0 + row0;
    const int gr1 = q0 + row1;
    #pragma unroll
    for (int nfd = 0; nfd < 8; nfd++) {
        const int col = nfd * 8 + 2 * tg;
        if (gr0 < TT)
            *(float2*)(O + (size_t)gr0 * EE + col) =
                make_float2(oacc[nfd][0] * inv0, oacc[nfd][1] * inv0);
        if (gr1 < TT)
            *(float2*)(O + (size_t)gr1 * EE + col) =
                make_float2(oacc[nfd][2] * inv1, oacc[nfd][3] * inv1);
    }
}

// ---------------------------------------------------------------------------
// Launch
// ---------------------------------------------------------------------------
extern "C" void kernel_launch(void* const* d_in, const int* in_sizes, int n_in,
                              void* d_out, int out_size)
{
    const float* x  = (const float*)d_in[0];
    const float* Wq = (const float*)d_in[1];
    const float* bq = (const float*)d_in[2];
    const float* Wk = (const float*)d_in[3];
    const float* bk = (const float*)d_in[4];
    const float* Wv = (const float*)d_in[5];
    const float* bv = (const float*)d_in[6];
    const float* Wo = (const float*)d_in[7];
    const float* bo = (const float*)d_in[8];
    float* out = (float*)d_out;

    float *gq, *gk, *gv, *ga;
    cudaGetSymbolAddress((void**)&gq, g_q);
    cudaGetSymbolAddress((void**)&gk, g_k);
    cudaGetSymbolAddress((void**)&gv, g_v);
    cudaGetSymbolAddress((void**)&ga, g_att);

    const int smemG = GSMEM_FLOATS * 4;   // 71680
    const int smemF = FSMEM_FLOATS * 4;   // 105472
    cudaFuncSetAttribute(gemm_tf32x3, cudaFuncAttributeMaxDynamicSharedMemorySize, smemG);
    cudaFuncSetAttribute(flash_attn_tc, cudaFuncAttributeMaxDynamicSharedMemorySize, smemF);

    dim3 gridG(EE / 128, (MM + 127) / 128);   // (8, 145)
    gemm_tf32x3<<<gridG, 256, smemG>>>(x, Wq, bq, gq, MM);
    gemm_tf32x3<<<gridG, 256, smemG>>>(x, Wk, bk, gk, MM);
    gemm_tf32x3<<<gridG, 256, smemG>>>(x, Wv, bv, gv, MM);

    dim3 gridA(BB * HH, (TT + FQB - 1) / FQB);  // (512, 5)
    flash_attn_tc<<<gridA, 256, smemF>>>(gq, gk, gv, ga);

    gemm_tf32x3<<<gridG, 256, smemG>>>(ga, Wo, bo, out, MM);
}

// round 8
// speedup vs baseline: 2.6677x; 1.1153x over previous
#include <cuda_runtime.h>
#include <cuda_bf16.h>
#include <math.h>
#include <stdint.h>

// Problem constants
#define BB 32
#define TT 577
#define EE 1024
#define HH 16
#define DD 64
#define MM (BB * TT)   // 18464 rows

// Scratch (alloc-free rule: __device__ globals)
__device__ float g_q[(size_t)MM * EE];
__device__ float g_k[(size_t)MM * EE];
__device__ float g_v[(size_t)MM * EE];
__device__ float g_att[(size_t)MM * EE];

// ---------------------------------------------------------------------------
// helpers
// ---------------------------------------------------------------------------
// 2-op split: hi = tf32_rna(x); lo = x - hi as raw fp32 bits.
// tf32 register operands are fp32-layout; HW ignores low mantissa bits, so the
// lo term is effectively RZ-rounded -> ~2^-22 relative impact. No second cvt.
__device__ __forceinline__ void split_u(float x, uint32_t& hi, uint32_t& lo) {
    uint32_t uh;
    asm("cvt.rna.tf32.f32 %0, %1;" : "=r"(uh) : "f"(x));
    hi = uh;
    lo = __float_as_uint(x - __uint_as_float(uh));
}

__device__ __forceinline__ void mma_tf32(float* acc,
                                         uint32_t a0, uint32_t a1, uint32_t a2, uint32_t a3,
                                         uint32_t b0, uint32_t b1) {
    asm volatile(
        "mma.sync.aligned.m16n8k8.row.col.f32.tf32.tf32.f32 "
        "{%0,%1,%2,%3}, {%4,%5,%6,%7}, {%8,%9}, {%0,%1,%2,%3};\n"
        : "+f"(acc[0]), "+f"(acc[1]), "+f"(acc[2]), "+f"(acc[3])
        : "r"(a0), "r"(a1), "r"(a2), "r"(a3), "r"(b0), "r"(b1));
}

__device__ __forceinline__ uint32_t smem_u32(const void* p) {
    return (uint32_t)__cvta_generic_to_shared(p);
}

// cp.async 16B with zero-fill when pred is false (src not accessed)
__device__ __forceinline__ void cp16(uint32_t dst, const void* src, bool pred) {
    asm volatile("cp.async.cg.shared.global [%0], [%1], 16, %2;\n"
                 :: "r"(dst), "l"(src), "r"(pred ? 16 : 0));
}
#define CP_COMMIT() asm volatile("cp.async.commit_group;\n" ::: "memory")
#define CP_WAIT0()  asm volatile("cp.async.wait_group 0;\n" ::: "memory")

// ---------------------------------------------------------------------------
// GEMM (3xTF32): C[M,1024] = A[M,1024] @ B[1024,1024] + bias
// Block tile 128x256, BK=32, 8 warps (2x4), warp tile 64x64.
// fp32 in smem (cp.async staged, double buffered); tf32 split at frag load.
// Dynamic smem: AS[2][128][36] + BS[2][32][264] = 104448 B. 1 CTA/SM.
// ---------------------------------------------------------------------------
#define GBN 256
#define GA_STRIDE 36
#define GB_STRIDE 264
#define GA_BUF (128 * GA_STRIDE)   // 4608 floats
#define GB_BUF (32 * GB_STRIDE)    // 8448 floats
#define GSMEM_FLOATS (2 * (GA_BUF + GB_BUF))   // 26112

__global__ __launch_bounds__(256, 1) void gemm_tf32x3(
    const float* __restrict__ A, const float* __restrict__ B,
    const float* __restrict__ bias, float* __restrict__ C, int M)
{
    extern __shared__ float sm[];
    float* AS = sm;                   // [2][128][36]
    float* BS = AS + 2 * GA_BUF;      // [2][32][264]
    const uint32_t sA = smem_u32(AS);
    const uint32_t sB = smem_u32(BS);

    const int tid  = threadIdx.x;
    const int lane = tid & 31;
    const int wid  = tid >> 5;
    const int g    = lane >> 2;       // 0..7
    const int tg   = lane & 3;        // 0..3
    const int wm   = (wid >> 2) * 64; // warp row offset (0/64)
    const int wn   = (wid & 3) * 64;  // warp col offset (0/64/128/192)
    const int rowBase = blockIdx.y * 128;
    const int colBase = blockIdx.x * GBN;

    float acc[4][8][4];
    #pragma unroll
    for (int mf = 0; mf < 4; mf++)
        #pragma unroll
        for (int nf = 0; nf < 8; nf++)
            #pragma unroll
            for (int c = 0; c < 4; c++) acc[mf][nf][c] = 0.f;

    auto issue = [&](int buf, int k0) {
        // A tile: 128 rows x 8 chunks = 1024
        #pragma unroll
        for (int i = 0; i < 4; i++) {
            const int idx = tid + i * 256;
            const int r = idx >> 3;
            const int c4 = (idx & 7) * 4;
            const int gr = rowBase + r;
            cp16(sA + (uint32_t)(buf * GA_BUF + r * GA_STRIDE + c4) * 4,
                 A + (size_t)gr * EE + k0 + c4, gr < M);
        }
        // B tile: 32 rows x 64 chunks = 2048
        #pragma unroll
        for (int i = 0; i < 8; i++) {
            const int idx = tid + i * 256;
            const int r = idx >> 6;
            const int c4 = (idx & 63) * 4;
            cp16(sB + (uint32_t)(buf * GB_BUF + r * GB_STRIDE + c4) * 4,
                 B + (size_t)(k0 + r) * EE + colBase + c4, true);
        }
        CP_COMMIT();
    };

    issue(0, 0);
    CP_WAIT0();
    __syncthreads();

    int buf = 0;
    for (int k0 = 0; k0 < EE; k0 += 32) {
        const bool more = (k0 + 32 < EE);
        if (more) issue(buf ^ 1, k0 + 32);   // DMA overlaps compute below

        const float* as = AS + buf * GA_BUF;
        const float* bs = BS + buf * GB_BUF;

        #pragma unroll
        for (int ks = 0; ks < 4; ks++) {
            uint32_t bHf[8][2], bLf[8][2];
            const int br0 = (ks * 8 + tg) * GB_STRIDE;
            const int br1 = br0 + 4 * GB_STRIDE;
            #pragma unroll
            for (int nf = 0; nf < 8; nf++) {
                const int col = wn + nf * 8 + g;
                split_u(bs[br0 + col], bHf[nf][0], bLf[nf][0]);
                split_u(bs[br1 + col], bHf[nf][1], bLf[nf][1]);
            }
            #pragma unroll
            for (int mf = 0; mf < 4; mf++) {
                const int r0 = (wm + mf * 16 + g) * GA_STRIDE + ks * 8 + tg;
                const int r1 = r0 + 8 * GA_STRIDE;
                uint32_t aH0, aH1, aH2, aH3, aL0, aL1, aL2, aL3;
                split_u(as[r0],     aH0, aL0);
                split_u(as[r1],     aH1, aL1);
                split_u(as[r0 + 4], aH2, aL2);
                split_u(as[r1 + 4], aH3, aL3);
                #pragma unroll
                for (int nf = 0; nf < 8; nf++) {
                    mma_tf32(acc[mf][nf], aH0, aH1, aH2, aH3, bHf[nf][0], bHf[nf][1]);
                    mma_tf32(acc[mf][nf], aL0, aL1, aL2, aL3, bHf[nf][0], bHf[nf][1]);
                    mma_tf32(acc[mf][nf], aH0, aH1, aH2, aH3, bLf[nf][0], bLf[nf][1]);
                }
            }
        }
        if (more) CP_WAIT0();
        __syncthreads();
        buf ^= 1;
    }

    #pragma unroll
    for (int mf = 0; mf < 4; mf++) {
        const int row = rowBase + wm + mf * 16 + g;
        #pragma unroll
        for (int nf = 0; nf < 8; nf++) {
            const int col = colBase + wn + nf * 8 + 2 * tg;
            const float b0 = bias[col];
            const float b1 = bias[col + 1];
            if (row < M) {
                float2 o0 = make_float2(acc[mf][nf][0] + b0, acc[mf][nf][1] + b1);
                *(float2*)(C + (size_t)row * EE + col) = o0;
            }
            if (row + 8 < M) {
                float2 o1 = make_float2(acc[mf][nf][2] + b0, acc[mf][nf][3] + b1);
                *(float2*)(C + (size_t)(row + 8) * EE + col) = o1;
            }
        }
    }
}

// ---------------------------------------------------------------------------
// Tensor-core flash attention (3xTF32), fp32 smem, register split (2-op).
// Block: 128 q-rows; k-tiles of 64. 8 warps; warp w owns q rows [16w,16w+16).
// Dynamic smem: Qs[128][68] Ks[64][68] Vs[64][72] Ps[128][68]
//             = 26368 floats = 105472 B -> 2 CTAs/SM.
// ---------------------------------------------------------------------------
#define FQB 128
#define FKB 64
#define QS 68
#define KS 68
#define VS 72
#define PS 68
#define FSMEM_FLOATS (128*QS + 64*KS + 64*VS + 128*PS)   // 26368

__global__ __launch_bounds__(256, 2) void flash_attn_tc(
    const float* __restrict__ q, const float* __restrict__ k,
    const float* __restrict__ v, float* __restrict__ o)
{
    extern __shared__ float sm[];
    float* Qs = sm;
    float* Ks = Qs + 128 * QS;
    float* Vs = Ks + 64 * KS;
    float* Ps = Vs + 64 * VS;
    const uint32_t sQ = smem_u32(Qs);
    const uint32_t sK = smem_u32(Ks);
    const uint32_t sV = smem_u32(Vs);

    const int tid  = threadIdx.x;
    const int lane = tid & 31;
    const int wid  = tid >> 5;       // 0..7
    const int g    = lane >> 2;      // 0..7
    const int tg   = lane & 3;       // 0..3

    const int bh = blockIdx.x;
    const int b = bh >> 4;
    const int h = bh & 15;
    const int q0 = blockIdx.y * FQB;

    const size_t base = (size_t)b * TT * EE + (size_t)h * DD;
    const float* Q = q + base;
    const float* K = k + base;
    const float* V = v + base;
    float* O = o + base;

    // ---- stage Q tile via cp.async: 128 rows x 16 chunks = 2048 ----
    #pragma unroll
    for (int i = 0; i < 8; i++) {
        const int idx = tid + i * 256;
        const int r = idx >> 4;
        const int c4 = (idx & 15) << 2;
        const int gr = q0 + r;
        cp16(sQ + (uint32_t)(r * QS + c4) * 4, Q + (size_t)gr * EE + c4, gr < TT);
    }
    CP_COMMIT();

    float m0 = -1e30f, m1 = -1e30f, l0 = 0.f, l1 = 0.f;
    float oacc[8][4];
    #pragma unroll
    for (int nf = 0; nf < 8; nf++)
        #pragma unroll
        for (int c = 0; c < 4; c++) oacc[nf][c] = 0.f;

    const int row0 = 16 * wid + g;   // local q rows owned by this lane
    const int row1 = row0 + 8;

    const int nkt = (TT + FKB - 1) / FKB;   // 10
    for (int kt = 0; kt < nkt; kt++) {
        const int kbase = kt * FKB;
        __syncthreads();   // prev iter K/V readers done

        // ---- stage K,V tile: 64 rows x 16 chunks = 1024 each ----
        #pragma unroll
        for (int i = 0; i < 4; i++) {
            const int idx = tid + i * 256;
            const int r = idx >> 4;
            const int c4 = (idx & 15) << 2;
            const int gr = kbase + r;
            cp16(sK + (uint32_t)(r * KS + c4) * 4, K + (size_t)gr * EE + c4, gr < TT);
            cp16(sV + (uint32_t)(r * VS + c4) * 4, V + (size_t)gr * EE + c4, gr < TT);
        }
        CP_COMMIT();
        CP_WAIT0();          // also covers the Q group on iter 0
        __syncthreads();

        // ---- S = Q K^T (3xTF32), warp computes 16 rows x 64 keys ----
        float sacc[8][4];
        #pragma unroll
        for (int nf = 0; nf < 8; nf++)
            #pragma unroll
            for (int c = 0; c < 4; c++) sacc[nf][c] = 0.f;

        #pragma unroll
        for (int kd = 0; kd < 8; kd++) {
            const int ar0 = row0 * QS + kd * 8 + tg;
            const int ar1 = ar0 + 8 * QS;
            uint32_t aH0, aH1, aH2, aH3, aL0, aL1, aL2, aL3;
            split_u(Qs[ar0],     aH0, aL0);
            split_u(Qs[ar1],     aH1, aL1);
            split_u(Qs[ar0 + 4], aH2, aL2);
            split_u(Qs[ar1 + 4], aH3, aL3);
            #pragma unroll
            for (int nf = 0; nf < 8; nf++) {
                const int br = (8 * nf + g) * KS + kd * 8 + tg;
                uint32_t bH0, bH1, bL0, bL1;
                split_u(Ks[br],     bH0, bL0);
                split_u(Ks[br + 4], bH1, bL1);
                mma_tf32(sacc[nf], aH0, aH1, aH2, aH3, bH0, bH1);
                mma_tf32(sacc[nf], aL0, aL1, aL2, aL3, bH0, bH1);
                mma_tf32(sacc[nf], aH0, aH1, aH2, aH3, bL0, bL1);
            }
        }

        // ---- scale + mask + row max ----
        float mx0 = -1e30f, mx1 = -1e30f;
        #pragma unroll
        for (int nf = 0; nf < 8; nf++) {
            const int kc0 = kbase + 8 * nf + 2 * tg;
            const int kc1 = kc0 + 1;
            sacc[nf][0] = (kc0 < TT) ? sacc[nf][0] * 0.125f : -1e30f;
            sacc[nf][1] = (kc1 < TT) ? sacc[nf][1] * 0.125f : -1e30f;
            sacc[nf][2] = (kc0 < TT) ? sacc[nf][2] * 0.125f : -1e30f;
            sacc[nf][3] = (kc1 < TT) ? sacc[nf][3] * 0.125f : -1e30f;
            mx0 = fmaxf(mx0, fmaxf(sacc[nf][0], sacc[nf][1]));
            mx1 = fmaxf(mx1, fmaxf(sacc[nf][2], sacc[nf][3]));
        }
        mx0 = fmaxf(mx0, __shfl_xor_sync(0xffffffffu, mx0, 1));
        mx0 = fmaxf(mx0, __shfl_xor_sync(0xffffffffu, mx0, 2));
        mx1 = fmaxf(mx1, __shfl_xor_sync(0xffffffffu, mx1, 1));
        mx1 = fmaxf(mx1, __shfl_xor_sync(0xffffffffu, mx1, 2));

        const float mn0 = fmaxf(m0, mx0);
        const float mn1 = fmaxf(m1, mx1);
        const float cc0 = __expf(m0 - mn0);
        const float cc1 = __expf(m1 - mn1);
        m0 = mn0; m1 = mn1;

        // ---- P = exp(s - m): store fp32 to smem, accumulate row sums ----
        float rs0 = 0.f, rs1 = 0.f;
        #pragma unroll
        for (int nf = 0; nf < 8; nf++) {
            const float p0 = __expf(sacc[nf][0] - m0);
            const float p1 = __expf(sacc[nf][1] - m0);
            const float p2 = __expf(sacc[nf][2] - m1);
            const float p3 = __expf(sacc[nf][3] - m1);
            rs0 += p0 + p1;
            rs1 += p2 + p3;
            const int col = 8 * nf + 2 * tg;
            *(float2*)&Ps[row0 * PS + col] = make_float2(p0, p1);
            *(float2*)&Ps[row1 * PS + col] = make_float2(p2, p3);
        }
        rs0 += __shfl_xor_sync(0xffffffffu, rs0, 1);
        rs0 += __shfl_xor_sync(0xffffffffu, rs0, 2);
        rs1 += __shfl_xor_sync(0xffffffffu, rs1, 1);
        rs1 += __shfl_xor_sync(0xffffffffu, rs1, 2);
        l0 = l0 * cc0 + rs0;
        l1 = l1 * cc1 + rs1;

        #pragma unroll
        for (int nf = 0; nf < 8; nf++) {
            oacc[nf][0] *= cc0;
            oacc[nf][1] *= cc0;
            oacc[nf][2] *= cc1;
            oacc[nf][3] *= cc1;
        }
        __syncwarp();   // P rows are warp-private: cross-lane visibility

        // ---- O += P V (3xTF32) ----
        #pragma unroll
        for (int kc = 0; kc < 8; kc++) {
            const int ar0 = row0 * PS + kc * 8 + tg;
            const int ar1 = ar0 + 8 * PS;
            uint32_t aH0, aH1, aH2, aH3, aL0, aL1, aL2, aL3;
            split_u(Ps[ar0],     aH0, aL0);
            split_u(Ps[ar1],     aH1, aL1);
            split_u(Ps[ar0 + 4], aH2, aL2);
            split_u(Ps[ar1 + 4], aH3, aL3);
            #pragma unroll
            for (int nfd = 0; nfd < 8; nfd++) {
                const int br0 = (kc * 8 + tg) * VS + nfd * 8 + g;
                const int br1 = br0 + 4 * VS;
                uint32_t bH0, bH1, bL0, bL1;
                split_u(Vs[br0], bH0, bL0);
                split_u(Vs[br1], bH1, bL1);
                mma_tf32(oacc[nfd], aH0, aH1, aH2, aH3, bH0, bH1);
                mma_tf32(oacc[nfd], aL0, aL1, aL2, aL3, bH0, bH1);
                mma_tf32(oacc[nfd], aH0, aH1, aH2, aH3, bL0, bL1);
            }
        }
    }

    // ---- epilogue: normalize + store ----
    const float inv0 = 1.f / l0;
    const float inv1 = 1.f / l1;
    const int gr0 = q0 + row0;
    const int gr1 = q0 + row1;
    #pragma unroll
    for (int nfd = 0; nfd < 8; nfd++) {
        const int col = nfd * 8 + 2 * tg;
        if (gr0 < TT)
            *(float2*)(O + (size_t)gr0 * EE + col) =
                make_float2(oacc[nfd][0] * inv0, oacc[nfd][1] * inv0);
        if (gr1 < TT)
            *(float2*)(O + (size_t)gr1 * EE + col) =
                make_float2(oacc[nfd][2] * inv1, oacc[nfd][3] * inv1);
    }
}

// ---------------------------------------------------------------------------
// Launch
// ---------------------------------------------------------------------------
extern "C" void kernel_launch(void* const* d_in, const int* in_sizes, int n_in,
                              void* d_out, int out_size)
{
    const float* x  = (const float*)d_in[0];
    const float* Wq = (const float*)d_in[1];
    const float* bq = (const float*)d_in[2];
    const float* Wk = (const float*)d_in[3];
    const float* bk = (const float*)d_in[4];
    const float* Wv = (const float*)d_in[5];
    const float* bv = (const float*)d_in[6];
    const float* Wo = (const float*)d_in[7];
    const float* bo = (const float*)d_in[8];
    float* out = (float*)d_out;

    float *gq, *gk, *gv, *ga;
    cudaGetSymbolAddress((void**)&gq, g_q);
    cudaGetSymbolAddress((void**)&gk, g_k);
    cudaGetSymbolAddress((void**)&gv, g_v);
    cudaGetSymbolAddress((void**)&ga, g_att);

    const int smemG = GSMEM_FLOATS * 4;   // 104448
    const int smemF = FSMEM_FLOATS * 4;   // 105472
    cudaFuncSetAttribute(gemm_tf32x3, cudaFuncAttributeMaxDynamicSharedMemorySize, smemG);
    cudaFuncSetAttribute(flash_attn_tc, cudaFuncAttributeMaxDynamicSharedMemorySize, smemF);

    dim3 gridG(EE / GBN, (MM + 127) / 128);   // (4, 145)
    gemm_tf32x3<<<gridG, 256, smemG>>>(x, Wq, bq, gq, MM);
    gemm_tf32x3<<<gridG, 256, smemG>>>(x, Wk, bk, gk, MM);
    gemm_tf32x3<<<gridG, 256, smemG>>>(x, Wv, bv, gv, MM);

    dim3 gridA(BB * HH, (TT + FQB - 1) / FQB);  // (512, 5)
    flash_attn_tc<<<gridA, 256, smemF>>>(gq, gk, gv, ga);

    gemm_tf32x3<<<gridG, 256, smemG>>>(ga, Wo, bo, out, MM);
}

// round 9
// speedup vs baseline: 3.7657x; 1.4116x over previous
#include <cuda_runtime.h>
#include <cuda_bf16.h>
#include <math.h>
#include <stdint.h>

// Problem constants
#define BB 32
#define TT 577
#define EE 1024
#define HH 16
#define DD 64
#define MM (BB * TT)   // 18464 rows

// Scratch (alloc-free rule: __device__ globals)
__device__ float g_q[(size_t)MM * EE];
__device__ float g_k[(size_t)MM * EE];
__device__ float g_v[(size_t)MM * EE];
__device__ float g_att[(size_t)MM * EE];

// ---------------------------------------------------------------------------
// helpers
// ---------------------------------------------------------------------------
// 2-op split: hi = tf32_rna(x); lo = x - hi as raw fp32 bits (lo ride RZ).
__device__ __forceinline__ void split_u(float x, uint32_t& hi, uint32_t& lo) {
    uint32_t uh;
    asm("cvt.rna.tf32.f32 %0, %1;" : "=r"(uh) : "f"(x));
    hi = uh;
    lo = __float_as_uint(x - __uint_as_float(uh));
}

// hi-only convert for the B operand (2xTF32: a*b ~= aH*bH + aL*bH)
__device__ __forceinline__ uint32_t cvt_hi(float x) {
    uint32_t uh;
    asm("cvt.rna.tf32.f32 %0, %1;" : "=r"(uh) : "f"(x));
    return uh;
}

__device__ __forceinline__ void mma_tf32(float* acc,
                                         uint32_t a0, uint32_t a1, uint32_t a2, uint32_t a3,
                                         uint32_t b0, uint32_t b1) {
    asm volatile(
        "mma.sync.aligned.m16n8k8.row.col.f32.tf32.tf32.f32 "
        "{%0,%1,%2,%3}, {%4,%5,%6,%7}, {%8,%9}, {%0,%1,%2,%3};\n"
        : "+f"(acc[0]), "+f"(acc[1]), "+f"(acc[2]), "+f"(acc[3])
        : "r"(a0), "r"(a1), "r"(a2), "r"(a3), "r"(b0), "r"(b1));
}

__device__ __forceinline__ uint32_t smem_u32(const void* p) {
    return (uint32_t)__cvta_generic_to_shared(p);
}

// cp.async 16B with zero-fill when pred is false (src not accessed)
__device__ __forceinline__ void cp16(uint32_t dst, const void* src, bool pred) {
    asm volatile("cp.async.cg.shared.global [%0], [%1], 16, %2;\n"
                 :: "r"(dst), "l"(src), "r"(pred ? 16 : 0));
}
#define CP_COMMIT() asm volatile("cp.async.commit_group;\n" ::: "memory")
#define CP_WAIT0()  asm volatile("cp.async.wait_group 0;\n" ::: "memory")

// ---------------------------------------------------------------------------
// GEMM (2xTF32): C[M,1024] = A[M,1024] @ B[1024,1024] + bias
// Block tile 128x256, BK=32, 8 warps (2x4), warp tile 64x64.
// A split hi/lo at frag load; B hi-only (dropped aH*bL term).
// Dynamic smem: AS[2][128][36] + BS[2][32][264] = 104448 B. 1 CTA/SM.
// ---------------------------------------------------------------------------
#define GBN 256
#define GA_STRIDE 36
#define GB_STRIDE 264
#define GA_BUF (128 * GA_STRIDE)   // 4608 floats
#define GB_BUF (32 * GB_STRIDE)    // 8448 floats
#define GSMEM_FLOATS (2 * (GA_BUF + GB_BUF))   // 26112

__global__ __launch_bounds__(256, 1) void gemm_tf32x2(
    const float* __restrict__ A, const float* __restrict__ B,
    const float* __restrict__ bias, float* __restrict__ C, int M)
{
    extern __shared__ float sm[];
    float* AS = sm;                   // [2][128][36]
    float* BS = AS + 2 * GA_BUF;      // [2][32][264]
    const uint32_t sA = smem_u32(AS);
    const uint32_t sB = smem_u32(BS);

    const int tid  = threadIdx.x;
    const int lane = tid & 31;
    const int wid  = tid >> 5;
    const int g    = lane >> 2;       // 0..7
    const int tg   = lane & 3;        // 0..3
    const int wm   = (wid >> 2) * 64; // warp row offset (0/64)
    const int wn   = (wid & 3) * 64;  // warp col offset (0/64/128/192)
    const int rowBase = blockIdx.y * 128;
    const int colBase = blockIdx.x * GBN;

    float acc[4][8][4];
    #pragma unroll
    for (int mf = 0; mf < 4; mf++)
        #pragma unroll
        for (int nf = 0; nf < 8; nf++)
            #pragma unroll
            for (int c = 0; c < 4; c++) acc[mf][nf][c] = 0.f;

    auto issue = [&](int buf, int k0) {
        // A tile: 128 rows x 8 chunks = 1024
        #pragma unroll
        for (int i = 0; i < 4; i++) {
            const int idx = tid + i * 256;
            const int r = idx >> 3;
            const int c4 = (idx & 7) * 4;
            const int gr = rowBase + r;
            cp16(sA + (uint32_t)(buf * GA_BUF + r * GA_STRIDE + c4) * 4,
                 A + (size_t)gr * EE + k0 + c4, gr < M);
        }
        // B tile: 32 rows x 64 chunks = 2048
        #pragma unroll
        for (int i = 0; i < 8; i++) {
            const int idx = tid + i * 256;
            const int r = idx >> 6;
            const int c4 = (idx & 63) * 4;
            cp16(sB + (uint32_t)(buf * GB_BUF + r * GB_STRIDE + c4) * 4,
                 B + (size_t)(k0 + r) * EE + colBase + c4, true);
        }
        CP_COMMIT();
    };

    issue(0, 0);
    CP_WAIT0();
    __syncthreads();

    int buf = 0;
    for (int k0 = 0; k0 < EE; k0 += 32) {
        const bool more = (k0 + 32 < EE);
        if (more) issue(buf ^ 1, k0 + 32);   // DMA overlaps compute below

        const float* as = AS + buf * GA_BUF;
        const float* bs = BS + buf * GB_BUF;

        #pragma unroll
        for (int ks = 0; ks < 4; ks++) {
            uint32_t bHf[8][2];
            const int br0 = (ks * 8 + tg) * GB_STRIDE;
            const int br1 = br0 + 4 * GB_STRIDE;
            #pragma unroll
            for (int nf = 0; nf < 8; nf++) {
                const int col = wn + nf * 8 + g;
                bHf[nf][0] = cvt_hi(bs[br0 + col]);
                bHf[nf][1] = cvt_hi(bs[br1 + col]);
            }
            #pragma unroll
            for (int mf = 0; mf < 4; mf++) {
                const int r0 = (wm + mf * 16 + g) * GA_STRIDE + ks * 8 + tg;
                const int r1 = r0 + 8 * GA_STRIDE;
                uint32_t aH0, aH1, aH2, aH3, aL0, aL1, aL2, aL3;
                split_u(as[r0],     aH0, aL0);
                split_u(as[r1],     aH1, aL1);
                split_u(as[r0 + 4], aH2, aL2);
                split_u(as[r1 + 4], aH3, aL3);
                #pragma unroll
                for (int nf = 0; nf < 8; nf++) {
                    mma_tf32(acc[mf][nf], aH0, aH1, aH2, aH3, bHf[nf][0], bHf[nf][1]);
                    mma_tf32(acc[mf][nf], aL0, aL1, aL2, aL3, bHf[nf][0], bHf[nf][1]);
                }
            }
        }
        if (more) CP_WAIT0();
        __syncthreads();
        buf ^= 1;
    }

    #pragma unroll
    for (int mf = 0; mf < 4; mf++) {
        const int row = rowBase + wm + mf * 16 + g;
        #pragma unroll
        for (int nf = 0; nf < 8; nf++) {
            const int col = colBase + wn + nf * 8 + 2 * tg;
            const float b0 = bias[col];
            const float b1 = bias[col + 1];
            if (row < M) {
                float2 o0 = make_float2(acc[mf][nf][0] + b0, acc[mf][nf][1] + b1);
                *(float2*)(C + (size_t)row * EE + col) = o0;
            }
            if (row + 8 < M) {
                float2 o1 = make_float2(acc[mf][nf][2] + b0, acc[mf][nf][3] + b1);
                *(float2*)(C + (size_t)(row + 8) * EE + col) = o1;
            }
        }
    }
}

// ---------------------------------------------------------------------------
// Tensor-core flash attention (2xTF32), fp32 smem, register split.
// Block: 128 q-rows; k-tiles of 64. 8 warps; warp w owns q rows [16w,16w+16).
// A operands (Q, P) split hi/lo; B operands (K, V) hi-only.
// Dynamic smem: Qs[128][68] Ks[64][68] Vs[64][72] Ps[128][68]
//             = 26368 floats = 105472 B -> 2 CTAs/SM.
// ---------------------------------------------------------------------------
#define FQB 128
#define FKB 64
#define QS 68
#define KS 68
#define VS 72
#define PS 68
#define FSMEM_FLOATS (128*QS + 64*KS + 64*VS + 128*PS)   // 26368

__global__ __launch_bounds__(256, 2) void flash_attn_tc(
    const float* __restrict__ q, const float* __restrict__ k,
    const float* __restrict__ v, float* __restrict__ o)
{
    extern __shared__ float sm[];
    float* Qs = sm;
    float* Ks = Qs + 128 * QS;
    float* Vs = Ks + 64 * KS;
    float* Ps = Vs + 64 * VS;
    const uint32_t sQ = smem_u32(Qs);
    const uint32_t sK = smem_u32(Ks);
    const uint32_t sV = smem_u32(Vs);

    const int tid  = threadIdx.x;
    const int lane = tid & 31;
    const int wid  = tid >> 5;       // 0..7
    const int g    = lane >> 2;      // 0..7
    const int tg   = lane & 3;       // 0..3

    const int bh = blockIdx.x;
    const int b = bh >> 4;
    const int h = bh & 15;
    const int q0 = blockIdx.y * FQB;

    const size_t base = (size_t)b * TT * EE + (size_t)h * DD;
    const float* Q = q + base;
    const float* K = k + base;
    const float* V = v + base;
    float* O = o + base;

    // ---- stage Q tile via cp.async: 128 rows x 16 chunks = 2048 ----
    #pragma unroll
    for (int i = 0; i < 8; i++) {
        const int idx = tid + i * 256;
        const int r = idx >> 4;
        const int c4 = (idx & 15) << 2;
        const int gr = q0 + r;
        cp16(sQ + (uint32_t)(r * QS + c4) * 4, Q + (size_t)gr * EE + c4, gr < TT);
    }
    CP_COMMIT();

    float m0 = -1e30f, m1 = -1e30f, l0 = 0.f, l1 = 0.f;
    float oacc[8][4];
    #pragma unroll
    for (int nf = 0; nf < 8; nf++)
        #pragma unroll
        for (int c = 0; c < 4; c++) oacc[nf][c] = 0.f;

    const int row0 = 16 * wid + g;   // local q rows owned by this lane
    const int row1 = row0 + 8;

    const int nkt = (TT + FKB - 1) / FKB;   // 10
    for (int kt = 0; kt < nkt; kt++) {
        const int kbase = kt * FKB;
        __syncthreads();   // prev iter K/V readers done

        // ---- stage K,V tile: 64 rows x 16 chunks = 1024 each ----
        #pragma unroll
        for (int i = 0; i < 4; i++) {
            const int idx = tid + i * 256;
            const int r = idx >> 4;
            const int c4 = (idx & 15) << 2;
            const int gr = kbase + r;
            cp16(sK + (uint32_t)(r * KS + c4) * 4, K + (size_t)gr * EE + c4, gr < TT);
            cp16(sV + (uint32_t)(r * VS + c4) * 4, V + (size_t)gr * EE + c4, gr < TT);
        }
        CP_COMMIT();
        CP_WAIT0();          // also covers the Q group on iter 0
        __syncthreads();

        // ---- S = Q K^T (2xTF32), warp computes 16 rows x 64 keys ----
        float sacc[8][4];
        #pragma unroll
        for (int nf = 0; nf < 8; nf++)
            #pragma unroll
            for (int c = 0; c < 4; c++) sacc[nf][c] = 0.f;

        #pragma unroll
        for (int kd = 0; kd < 8; kd++) {
            const int ar0 = row0 * QS + kd * 8 + tg;
            const int ar1 = ar0 + 8 * QS;
            uint32_t aH0, aH1, aH2, aH3, aL0, aL1, aL2, aL3;
            split_u(Qs[ar0],     aH0, aL0);
            split_u(Qs[ar1],     aH1, aL1);
            split_u(Qs[ar0 + 4], aH2, aL2);
            split_u(Qs[ar1 + 4], aH3, aL3);
            #pragma unroll
            for (int nf = 0; nf < 8; nf++) {
                const int br = (8 * nf + g) * KS + kd * 8 + tg;
                const uint32_t bH0 = cvt_hi(Ks[br]);
                const uint32_t bH1 = cvt_hi(Ks[br + 4]);
                mma_tf32(sacc[nf], aH0, aH1, aH2, aH3, bH0, bH1);
                mma_tf32(sacc[nf], aL0, aL1, aL2, aL3, bH0, bH1);
            }
        }

        // ---- scale + mask + row max ----
        float mx0 = -1e30f, mx1 = -1e30f;
        #pragma unroll
        for (int nf = 0; nf < 8; nf++) {
            const int kc0 = kbase + 8 * nf + 2 * tg;
            const int kc1 = kc0 + 1;
            sacc[nf][0] = (kc0 < TT) ? sacc[nf][0] * 0.125f : -1e30f;
            sacc[nf][1] = (kc1 < TT) ? sacc[nf][1] * 0.125f : -1e30f;
            sacc[nf][2] = (kc0 < TT) ? sacc[nf][2] * 0.125f : -1e30f;
            sacc[nf][3] = (kc1 < TT) ? sacc[nf][3] * 0.125f : -1e30f;
            mx0 = fmaxf(mx0, fmaxf(sacc[nf][0], sacc[nf][1]));
            mx1 = fmaxf(mx1, fmaxf(sacc[nf][2], sacc[nf][3]));
        }
        mx0 = fmaxf(mx0, __shfl_xor_sync(0xffffffffu, mx0, 1));
        mx0 = fmaxf(mx0, __shfl_xor_sync(0xffffffffu, mx0, 2));
        mx1 = fmaxf(mx1, __shfl_xor_sync(0xffffffffu, mx1, 1));
        mx1 = fmaxf(mx1, __shfl_xor_sync(0xffffffffu, mx1, 2));

        const float mn0 = fmaxf(m0, mx0);
        const float mn1 = fmaxf(m1, mx1);
        const float cc0 = __expf(m0 - mn0);
        const float cc1 = __expf(m1 - mn1);
        m0 = mn0; m1 = mn1;

        // ---- P = exp(s - m): store fp32 to smem, accumulate row sums ----
        float rs0 = 0.f, rs1 = 0.f;
        #pragma unroll
        for (int nf = 0; nf < 8; nf++) {
            const float p0 = __expf(sacc[nf][0] - m0);
            const float p1 = __expf(sacc[nf][1] - m0);
            const float p2 = __expf(sacc[nf][2] - m1);
            const float p3 = __expf(sacc[nf][3] - m1);
            rs0 += p0 + p1;
            rs1 += p2 + p3;
            const int col = 8 * nf + 2 * tg;
            *(float2*)&Ps[row0 * PS + col] = make_float2(p0, p1);
            *(float2*)&Ps[row1 * PS + col] = make_float2(p2, p3);
        }
        rs0 += __shfl_xor_sync(0xffffffffu, rs0, 1);
        rs0 += __shfl_xor_sync(0xffffffffu, rs0, 2);
        rs1 += __shfl_xor_sync(0xffffffffu, rs1, 1);
        rs1 += __shfl_xor_sync(0xffffffffu, rs1, 2);
        l0 = l0 * cc0 + rs0;
        l1 = l1 * cc1 + rs1;

        #pragma unroll
        for (int nf = 0; nf < 8; nf++) {
            oacc[nf][0] *= cc0;
            oacc[nf][1] *= cc0;
            oacc[nf][2] *= cc1;
            oacc[nf][3] *= cc1;
        }
        __syncwarp();   // P rows are warp-private: cross-lane visibility

        // ---- O += P V (2xTF32) ----
        #pragma unroll
        for (int kc = 0; kc < 8; kc++) {
            const int ar0 = row0 * PS + kc * 8 + tg;
            const int ar1 = ar0 + 8 * PS;
            uint32_t aH0, aH1, aH2, aH3, aL0, aL1, aL2, aL3;
            split_u(Ps[ar0],     aH0, aL0);
            split_u(Ps[ar1],     aH1, aL1);
            split_u(Ps[ar0 + 4], aH2, aL2);
            split_u(Ps[ar1 + 4], aH3, aL3);
            #pragma unroll
            for (int nfd = 0; nfd < 8; nfd++) {
                const int br0 = (kc * 8 + tg) * VS + nfd * 8 + g;
                const int br1 = br0 + 4 * VS;
                const uint32_t bH0 = cvt_hi(Vs[br0]);
                const uint32_t bH1 = cvt_hi(Vs[br1]);
                mma_tf32(oacc[nfd], aH0, aH1, aH2, aH3, bH0, bH1);
                mma_tf32(oacc[nfd], aL0, aL1, aL2, aL3, bH0, bH1);
            }
        }
    }

    // ---- epilogue: normalize + store ----
    const float inv0 = 1.f / l0;
    const float inv1 = 1.f / l1;
    const int gr0 = q0 + row0;
    const int gr1 = q0 + row1;
    #pragma unroll
    for (int nfd = 0; nfd < 8; nfd++) {
        const int col = nfd * 8 + 2 * tg;
        if (gr0 < TT)
            *(float2*)(O + (size_t)gr0 * EE + col) =
                make_float2(oacc[nfd][0] * inv0, oacc[nfd][1] * inv0);
        if (gr1 < TT)
            *(float2*)(O + (size_t)gr1 * EE + col) =
                make_float2(oacc[nfd][2] * inv1, oacc[nfd][3] * inv1);
    }
}

// ---------------------------------------------------------------------------
// Launch
// ---------------------------------------------------------------------------
extern "C" void kernel_launch(void* const* d_in, const int* in_sizes, int n_in,
                              void* d_out, int out_size)
{
    const float* x  = (const float*)d_in[0];
    const float* Wq = (const float*)d_in[1];
    const float* bq = (const float*)d_in[2];
    const float* Wk = (const float*)d_in[3];
    const float* bk = (const float*)d_in[4];
    const float* Wv = (const float*)d_in[5];
    const float* bv = (const float*)d_in[6];
    const float* Wo = (const float*)d_in[7];
    const float* bo = (const float*)d_in[8];
    float* out = (float*)d_out;

    float *gq, *gk, *gv, *ga;
    cudaGetSymbolAddress((void**)&gq, g_q);
    cudaGetSymbolAddress((void**)&gk, g_k);
    cudaGetSymbolAddress((void**)&gv, g_v);
    cudaGetSymbolAddress((void**)&ga, g_att);

    const int smemG = GSMEM_FLOATS * 4;   // 104448
    const int smemF = FSMEM_FLOATS * 4;   // 105472
    cudaFuncSetAttribute(gemm_tf32x2, cudaFuncAttributeMaxDynamicSharedMemorySize, smemG);
    cudaFuncSetAttribute(flash_attn_tc, cudaFuncAttributeMaxDynamicSharedMemorySize, smemF);

    dim3 gridG(EE / GBN, (MM + 127) / 128);   // (4, 145)
    gemm_tf32x2<<<gridG, 256, smemG>>>(x, Wq, bq, gq, MM);
    gemm_tf32x2<<<gridG, 256, smemG>>>(x, Wk, bk, gk, MM);
    gemm_tf32x2<<<gridG, 256, smemG>>>(x, Wv, bv, gv, MM);

    dim3 gridA(BB * HH, (TT + FQB - 1) / FQB);  // (512, 5)
    flash_attn_tc<<<gridA, 256, smemF>>>(gq, gk, gv, ga);

    gemm_tf32x2<<<gridG, 256, smemG>>>(ga, Wo, bo, out, MM);
}